// round 8
// baseline (speedup 1.0000x reference)
#include <cuda_runtime.h>
#include <math.h>

// Problem constants (fixed by the reference)
#define NN 50000
#define NE 800000
#define INC 128
#define OUTC 64
#define HEADS 4
#define HC (HEADS * OUTC)   // 256
#define NEG_SLOPE 0.2f
#define ET (NE + NN)        // edges + self-loops

// ---------------- scratch (device globals) -----------------------------------
__device__ float g_h[(size_t)NN * HC];      // projected features [N,256]
__device__ float g_asrc[NN * HEADS];        // per-node att halves
__device__ float g_adst[NN * HEADS];
__device__ float g_den[NN * HEADS];         // segment sum of exp
__device__ int   g_is64;                    // edge_index dtype flag

// ---------------- helpers -----------------------------------------------------
__device__ __forceinline__ float lrelu(float v) {
    return v >= 0.0f ? v : NEG_SLOPE * v;
}

__device__ __forceinline__ int edge_at(const void* ei, long long idx) {
    if (g_is64) return (int)((const long long*)ei)[idx];
    return ((const int*)ei)[idx];
}

__device__ __forceinline__ unsigned long long pack2(float lo, float hi) {
    unsigned long long r;
    asm("mov.b64 %0, {%1, %2};" : "=l"(r) : "f"(lo), "f"(hi));
    return r;
}
__device__ __forceinline__ void unpack2(unsigned long long v, float& lo, float& hi) {
    asm("mov.b64 {%0, %1}, %2;" : "=f"(lo), "=f"(hi) : "l"(v));
}
__device__ __forceinline__ unsigned long long fma2(
    unsigned long long a, unsigned long long b, unsigned long long c) {
    unsigned long long d;
    asm("fma.rn.f32x2 %0, %1, %2, %3;" : "=l"(d) : "l"(a), "l"(b), "l"(c));
    return d;
}

__device__ __forceinline__ void red_add_v4(float* addr, float4 v) {
    asm volatile("red.global.add.v4.f32 [%0], {%1, %2, %3, %4};"
                 :: "l"(addr), "f"(v.x), "f"(v.y), "f"(v.z), "f"(v.w)
                 : "memory");
}

// ---------------- 0) dtype detection ------------------------------------------
__global__ void detect_kernel(const int* __restrict__ ei_raw) {
    __shared__ int nz;
    if (threadIdx.x == 0) nz = 0;
    __syncthreads();
    int local = 0;
    for (int i = threadIdx.x; i < 4096; i += blockDim.x)
        if (ei_raw[2 * i + 1] != 0) local = 1;
    if (local) atomicOr(&nz, 1);
    __syncthreads();
    if (threadIdx.x == 0) g_is64 = (nz == 0) ? 1 : 0;
}

// ---------------- 1) zero kernels ----------------------------------------------
__global__ void zero_den_kernel() {
    int i = blockIdx.x * blockDim.x + threadIdx.x;
    if (i < NN * HEADS) g_den[i] = 0.0f;
}
__global__ void zero_out_kernel(float* __restrict__ out) {
    int i = blockIdx.x * blockDim.x + threadIdx.x;
    if (i < NN * OUTC / 4)
        ((float4*)out)[i] = make_float4(0.f, 0.f, 0.f, 0.f);
}

// ---------------- 2) SGEMM + fused attention halves ----------------------------
// CTA: 32 rows x 256 cols, 128 threads, 8x8 microtile, f32x2 packed FMA.
// Small CTAs -> 4 independent barrier domains per SM for pipe overlap.
__global__ __launch_bounds__(128, 4) void gemm_kernel(
    const float* __restrict__ x, const float* __restrict__ W,
    const float* __restrict__ att_src, const float* __restrict__ att_dst)
{
    __shared__ float xs[32][32];    // [k][row]   4KB
    __shared__ float ws[32][256];   // [k][col]  32KB

    const int tid = threadIdx.x;
    const int tcol = tid & 31;      // 32 col groups of 8
    const int trow = tid >> 5;      // 4 row groups of 8
    const int rowBase = blockIdx.x * 32;

    unsigned long long acc2[8][4];
#pragma unroll
    for (int r = 0; r < 8; r++)
#pragma unroll
        for (int c = 0; c < 4; c++) acc2[r][c] = 0ull;

    for (int k0 = 0; k0 < INC; k0 += 32) {
        // x tile: 32 rows x 32 k = 256 float4, 2 per thread
#pragma unroll
        for (int i = 0; i < 2; i++) {
            int t = tid + i * 128;
            int r = t >> 3;               // 0..31
            int kk = (t & 7) * 4;
            float4 v = make_float4(0.f, 0.f, 0.f, 0.f);
            int gr = rowBase + r;
            if (gr < NN) v = *(const float4*)&x[(size_t)gr * INC + k0 + kk];
            xs[kk + 0][r] = v.x; xs[kk + 1][r] = v.y;
            xs[kk + 2][r] = v.z; xs[kk + 3][r] = v.w;
        }
        // W tile: 256 cols x 32 k = 2048 float4, 16 per thread
#pragma unroll
        for (int i = 0; i < 16; i++) {
            int t = tid + i * 128;
            int c = t >> 3;               // 0..255
            int kk = (t & 7) * 4;
            float4 v = *(const float4*)&W[(size_t)c * INC + k0 + kk];
            ws[kk + 0][c] = v.x; ws[kk + 1][c] = v.y;
            ws[kk + 2][c] = v.z; ws[kk + 3][c] = v.w;
        }
        __syncthreads();

#pragma unroll
        for (int k = 0; k < 32; k++) {
            float4 xa = *(const float4*)&xs[k][trow * 8];
            float4 xb = *(const float4*)&xs[k][trow * 8 + 4];
            ulonglong2 w0 = *(const ulonglong2*)&ws[k][tcol * 8];
            ulonglong2 w1 = *(const ulonglong2*)&ws[k][tcol * 8 + 4];
            unsigned long long wv[4] = {w0.x, w0.y, w1.x, w1.y};
            float xv[8] = {xa.x, xa.y, xa.z, xa.w, xb.x, xb.y, xb.z, xb.w};
#pragma unroll
            for (int r = 0; r < 8; r++) {
                unsigned long long xp = pack2(xv[r], xv[r]);
#pragma unroll
                for (int c = 0; c < 4; c++)
                    acc2[r][c] = fma2(xp, wv[c], acc2[r][c]);
            }
        }
        __syncthreads();
    }

    float acc[8][8];
#pragma unroll
    for (int r = 0; r < 8; r++)
#pragma unroll
        for (int c = 0; c < 4; c++)
            unpack2(acc2[r][c], acc[r][2 * c], acc[r][2 * c + 1]);

    // store h
#pragma unroll
    for (int r = 0; r < 8; r++) {
        int gr = rowBase + trow * 8 + r;
        if (gr >= NN) continue;
        float* hp = &g_h[(size_t)gr * HC + tcol * 8];
        *(float4*)&hp[0] = *(float4*)&acc[r][0];
        *(float4*)&hp[4] = *(float4*)&acc[r][4];
    }

    // fused attention halves: head = tcol>>3, within-head offset (tcol&7)*8
    const int head = tcol >> 3;
    const int off = (tcol & 7) * 8;
    float av[8], bv[8];
    *(float4*)&av[0] = *(const float4*)&att_src[head * OUTC + off];
    *(float4*)&av[4] = *(const float4*)&att_src[head * OUTC + off + 4];
    *(float4*)&bv[0] = *(const float4*)&att_dst[head * OUTC + off];
    *(float4*)&bv[4] = *(const float4*)&att_dst[head * OUTC + off + 4];
#pragma unroll
    for (int r = 0; r < 8; r++) {
        float s = 0.0f, d = 0.0f;
#pragma unroll
        for (int q = 0; q < 8; q++) {
            s = fmaf(acc[r][q], av[q], s);
            d = fmaf(acc[r][q], bv[q], d);
        }
        s += __shfl_xor_sync(0xffffffffu, s, 1);
        s += __shfl_xor_sync(0xffffffffu, s, 2);
        s += __shfl_xor_sync(0xffffffffu, s, 4);
        d += __shfl_xor_sync(0xffffffffu, d, 1);
        d += __shfl_xor_sync(0xffffffffu, d, 2);
        d += __shfl_xor_sync(0xffffffffu, d, 4);
        int gr = rowBase + trow * 8 + r;
        if ((tcol & 7) == 0 && gr < NN) {
            g_asrc[gr * HEADS + head] = s;
            g_adst[gr * HEADS + head] = d;
        }
    }
}

// ---------------- 3) edge pass: denominator accumulation only ------------------
__global__ void edge_kernel(const void* __restrict__ ei)
{
    int e = blockIdx.x * blockDim.x + threadIdx.x;
    if (e >= ET) return;
    int src, dst;
    if (e < NE) {
        src = edge_at(ei, e);
        dst = edge_at(ei, (long long)NE + e);
    } else {
        src = dst = e - NE;
    }
    float4 as = *(const float4*)&g_asrc[src * HEADS];
    float4 ad = *(const float4*)&g_adst[dst * HEADS];
    float4 ex;
    ex.x = __expf(lrelu(as.x + ad.x));
    ex.y = __expf(lrelu(as.y + ad.y));
    ex.z = __expf(lrelu(as.z + ad.z));
    ex.w = __expf(lrelu(as.w + ad.w));
    red_add_v4(&g_den[dst * HEADS], ex);
}

// ---------------- 4) weighted scatter (ex recomputed, head-mean folded) --------
__global__ __launch_bounds__(256) void scatter_kernel(
    const void* __restrict__ ei, float* __restrict__ out)
{
    int gtid = blockIdx.x * blockDim.x + threadIdx.x;
    int e = (gtid >> 5) * 2 + ((gtid & 31) >> 4);
    int j = gtid & 15;
    if (e >= ET) return;
    int src, dst;
    if (e < NE) {
        src = edge_at(ei, e);
        dst = edge_at(ei, (long long)NE + e);
    } else {
        src = dst = e - NE;
    }
    float4 as = *(const float4*)&g_asrc[src * HEADS];
    float4 ad = *(const float4*)&g_adst[dst * HEADS];
    float4 dn = *(const float4*)&g_den[dst * HEADS];
    float a0 = 0.25f * __expf(lrelu(as.x + ad.x)) / dn.x;
    float a1 = 0.25f * __expf(lrelu(as.y + ad.y)) / dn.y;
    float a2 = 0.25f * __expf(lrelu(as.z + ad.z)) / dn.z;
    float a3 = 0.25f * __expf(lrelu(as.w + ad.w)) / dn.w;

    const float4* hp = (const float4*)&g_h[(size_t)src * HC];
    float4 h0 = hp[j];
    float4 h1 = hp[16 + j];
    float4 h2 = hp[32 + j];
    float4 h3 = hp[48 + j];
    float4 v;
    v.x = a0 * h0.x + a1 * h1.x + a2 * h2.x + a3 * h3.x;
    v.y = a0 * h0.y + a1 * h1.y + a2 * h2.y + a3 * h3.y;
    v.z = a0 * h0.z + a1 * h1.z + a2 * h2.z + a3 * h3.z;
    v.w = a0 * h0.w + a1 * h1.w + a2 * h2.w + a3 * h3.w;
    red_add_v4(&out[(size_t)dst * OUTC + 4 * j], v);
}

// ---------------- 5) finalize: bias + ReLU in place ----------------------------
__global__ void final_kernel(float* __restrict__ out, const float* __restrict__ bias)
{
    int i = blockIdx.x * blockDim.x + threadIdx.x;
    if (i >= NN * OUTC) return;
    float v = out[i] + bias[i & (OUTC - 1)];
    out[i] = fmaxf(v, 0.0f);
}

// ---------------- launch --------------------------------------------------------
extern "C" void kernel_launch(void* const* d_in, const int* in_sizes, int n_in,
                              void* d_out, int out_size)
{
    const float* x       = (const float*)d_in[0];
    const void*  ei      = d_in[1];
    const float* W       = (const float*)d_in[2];
    const float* att_src = (const float*)d_in[3];
    const float* att_dst = (const float*)d_in[4];
    const float* bias    = (const float*)d_in[5];
    float* out = (float*)d_out;

    detect_kernel<<<1, 256>>>((const int*)ei);                       // idx 0
    zero_den_kernel<<<(NN * HEADS + 255) / 256, 256>>>();            // idx 1
    zero_out_kernel<<<(NN * OUTC / 4 + 255) / 256, 256>>>(out);      // idx 2
    gemm_kernel<<<(NN + 31) / 32, 128>>>(x, W, att_src, att_dst);    // idx 3 (profiled)
    edge_kernel<<<(ET + 255) / 256, 256>>>(ei);                      // idx 4
    scatter_kernel<<<((size_t)ET * 16 + 255) / 256, 256>>>(ei, out); // idx 5
    final_kernel<<<(NN * OUTC + 255) / 256, 256>>>(out, bias);       // idx 6
}

// round 10
// speedup vs baseline: 1.4238x; 1.4238x over previous
#include <cuda_runtime.h>
#include <cuda_bf16.h>
#include <math.h>
#include <cstdint>

#define NN 50000
#define NE 800000
#define INC 128
#define OUTC 64
#define HEADS 4
#define HC (HEADS * OUTC)   // 256
#define NEG_SLOPE 0.2f
#define ET (NE + NN)

// ---------------- scratch ------------------------------------------------------
__device__ float g_h[(size_t)NN * HC];
__device__ float g_asrc[NN * HEADS];
__device__ float g_adst[NN * HEADS];
__device__ float g_den[NN * HEADS];
__device__ int   g_is64;

// ---------------- helpers ------------------------------------------------------
__device__ __forceinline__ float lrelu(float v) {
    return v >= 0.0f ? v : NEG_SLOPE * v;
}
__device__ __forceinline__ int edge_at(const void* ei, long long idx) {
    if (g_is64) return (int)((const long long*)ei)[idx];
    return ((const int*)ei)[idx];
}
__device__ __forceinline__ void red_add_v4(float* addr, float4 v) {
    asm volatile("red.global.add.v4.f32 [%0], {%1, %2, %3, %4};"
                 :: "l"(addr), "f"(v.x), "f"(v.y), "f"(v.z), "f"(v.w)
                 : "memory");
}
__device__ __forceinline__ uint32_t smem_to_u32(const void* p) {
    uint32_t a;
    asm("{ .reg .u64 t; cvta.to.shared.u64 t, %1; cvt.u32.u64 %0, t; }"
        : "=r"(a) : "l"(p));
    return a;
}
__device__ __forceinline__ uint32_t pack_bf16x2(float lo, float hi) {
    __nv_bfloat162 p(__float2bfloat16(lo), __float2bfloat16(hi));
    return *(uint32_t*)&p;
}
__device__ __forceinline__ float bf_round(float v) {
    return __bfloat162float(__float2bfloat16(v));
}

#define LDSM_X4(r0, r1, r2, r3, a) \
    asm volatile("ldmatrix.sync.aligned.m8n8.x4.shared.b16 {%0,%1,%2,%3}, [%4];" \
                 : "=r"(r0), "=r"(r1), "=r"(r2), "=r"(r3) : "r"(a))

#define MMA_BF16(c, a0, a1, a2, a3, b0, b1) \
    asm volatile("mma.sync.aligned.m16n8k16.row.col.f32.bf16.bf16.f32 " \
                 "{%0,%1,%2,%3}, {%4,%5,%6,%7}, {%8,%9}, {%0,%1,%2,%3};" \
                 : "+f"((c)[0]), "+f"((c)[1]), "+f"((c)[2]), "+f"((c)[3]) \
                 : "r"(a0), "r"(a1), "r"(a2), "r"(a3), "r"(b0), "r"(b1))

// ---------------- 0) dtype detection -------------------------------------------
__global__ void detect_kernel(const int* __restrict__ ei_raw) {
    __shared__ int nz;
    if (threadIdx.x == 0) nz = 0;
    __syncthreads();
    int local = 0;
    for (int i = threadIdx.x; i < 4096; i += blockDim.x)
        if (ei_raw[2 * i + 1] != 0) local = 1;
    if (local) atomicOr(&nz, 1);
    __syncthreads();
    if (threadIdx.x == 0) g_is64 = (nz == 0) ? 1 : 0;
}

// ---------------- 1) zero kernels -----------------------------------------------
__global__ void zero_den_kernel() {
    int i = blockIdx.x * blockDim.x + threadIdx.x;
    if (i < NN * HEADS) g_den[i] = 0.0f;
}
__global__ void zero_out_kernel(float* __restrict__ out) {
    int i = blockIdx.x * blockDim.x + threadIdx.x;
    if (i < NN * OUTC / 4)
        ((float4*)out)[i] = make_float4(0.f, 0.f, 0.f, 0.f);
}

// ---------------- 2) HMMA split-bf16 GEMM + fused attention halves --------------
// CTA 512 thr: tile M=128 x N=256, K chunks of 32. smem stride 40 bf16 (80B).
// h = xh*wh + xh*wl + xl*wh
#define KCH 32
#define STR 40                      // bf16 elements per smem row
#define AH_OFF 0                    // 128*40*2 = 10240
#define AL_OFF 10240
#define BH_OFF 20480                // 256*40*2 = 20480
#define BL_OFF 40960
#define GSMEM 61440

__global__ __launch_bounds__(512) void gemm_tc_kernel(
    const float* __restrict__ x, const float* __restrict__ W,
    const float* __restrict__ att_src, const float* __restrict__ att_dst)
{
    extern __shared__ char smem[];
    const uint32_t sbase = smem_to_u32(smem);
    const int tid = threadIdx.x;
    const int wid = tid >> 5;
    const int lane = tid & 31;
    const int rowBase = blockIdx.x * 128;

    // warp tiling: 8 row-groups x 2 col-groups
    const int wr = wid & 7;          // row group: rows wr*16..+15
    const int wc = wid >> 3;         // col group: cols wc*128..+127
    const int R0 = wr * 16;
    const int N0 = wc * 128;

    // ldmatrix lane geometry
    const int lrow = lane & 7;
    const int quad = lane >> 3;

    // A frag address (ks=0): row = R0 + (quad&1)*8 + lrow, col = (quad>>1)*8
    const uint32_t addrA0 = sbase + AH_OFF +
        ((R0 + (quad & 1) * 8 + lrow) * STR + (quad >> 1) * 8) * 2;
    // B frag address (ks=0, tile-pair 0): row = N0 + (quad>>1)*8 + lrow, col = (quad&1)*8
    const uint32_t addrB0 = sbase + BH_OFF +
        ((N0 + (quad >> 1) * 8 + lrow) * STR + (quad & 1) * 8) * 2;

    float c[16][4];
#pragma unroll
    for (int t = 0; t < 16; t++)
#pragma unroll
        for (int q = 0; q < 4; q++) c[t][q] = 0.0f;

    // conversion thread mapping
    const int xrow = tid >> 2;            // 0..127
    const int xkp = (tid & 3) * 8;        // 0,8,16,24
    const int wrow = tid >> 1;            // 0..255
    const int wkp = (tid & 1) * 16;       // 0,16

    for (int kc = 0; kc < 4; kc++) {
        const int k0 = kc * KCH;
        // ---- convert x chunk: 128 rows x 32 k ----
        {
            int gr = rowBase + xrow;
            float4 v0 = make_float4(0.f, 0.f, 0.f, 0.f), v1 = v0;
            if (gr < NN) {
                const float4* xp = (const float4*)(x + (size_t)gr * INC + k0 + xkp);
                v0 = __ldg(&xp[0]);
                v1 = __ldg(&xp[1]);
            }
            float f[8] = {v0.x, v0.y, v0.z, v0.w, v1.x, v1.y, v1.z, v1.w};
            uint32_t* ah = (uint32_t*)(smem + AH_OFF + (xrow * STR + xkp) * 2);
            uint32_t* al = (uint32_t*)(smem + AL_OFF + (xrow * STR + xkp) * 2);
#pragma unroll
            for (int j = 0; j < 4; j++) {
                float a = f[2 * j], b = f[2 * j + 1];
                ah[j] = pack_bf16x2(a, b);
                al[j] = pack_bf16x2(a - bf_round(a), b - bf_round(b));
            }
        }
        // ---- convert W chunk: 256 rows x 32 k ----
        {
            const float4* wp = (const float4*)(W + (size_t)wrow * INC + k0 + wkp);
            float4 v0 = __ldg(&wp[0]);
            float4 v1 = __ldg(&wp[1]);
            float4 v2 = __ldg(&wp[2]);
            float4 v3 = __ldg(&wp[3]);
            float f[16] = {v0.x, v0.y, v0.z, v0.w, v1.x, v1.y, v1.z, v1.w,
                           v2.x, v2.y, v2.z, v2.w, v3.x, v3.y, v3.z, v3.w};
            uint32_t* bh = (uint32_t*)(smem + BH_OFF + (wrow * STR + wkp) * 2);
            uint32_t* bl = (uint32_t*)(smem + BL_OFF + (wrow * STR + wkp) * 2);
#pragma unroll
            for (int j = 0; j < 8; j++) {
                float a = f[2 * j], b = f[2 * j + 1];
                bh[j] = pack_bf16x2(a, b);
                bl[j] = pack_bf16x2(a - bf_round(a), b - bf_round(b));
            }
        }
        __syncthreads();

        // ---- compute: 2 k-steps of 16 ----
#pragma unroll
        for (int ks = 0; ks < 2; ks++) {
            const uint32_t aAH = addrA0 + ks * 32;       // +16 bf16
            uint32_t ah0, ah1, ah2, ah3, al0, al1, al2, al3;
            LDSM_X4(ah0, ah1, ah2, ah3, aAH);
            LDSM_X4(al0, al1, al2, al3, aAH + AL_OFF);

            uint32_t aB = addrB0 + ks * 32;
#pragma unroll
            for (int tp = 0; tp < 8; tp++) {
                uint32_t bh0, bh1, bh2, bh3, bl0, bl1, bl2, bl3;
                LDSM_X4(bh0, bh1, bh2, bh3, aB);
                LDSM_X4(bl0, bl1, bl2, bl3, aB + 20480); // BL_OFF - BH_OFF
                const int t = tp * 2;
                MMA_BF16(c[t],     ah0, ah1, ah2, ah3, bh0, bh1);
                MMA_BF16(c[t],     ah0, ah1, ah2, ah3, bl0, bl1);
                MMA_BF16(c[t],     al0, al1, al2, al3, bh0, bh1);
                MMA_BF16(c[t + 1], ah0, ah1, ah2, ah3, bh2, bh3);
                MMA_BF16(c[t + 1], ah0, ah1, ah2, ah3, bl2, bl3);
                MMA_BF16(c[t + 1], al0, al1, al2, al3, bh2, bh3);
                aB += 16 * STR * 2;   // next 16 n-rows
            }
        }
        __syncthreads();
    }

    // ---- epilogue ----
    // thread covers rows row0 = rowBase+R0+gid, row1 = row0+8;
    // tile t cols: N0 + t*8 + tig*2 (+1). c[t] = {r0c0, r0c1, r1c0, r1c1}
    const int gid = lane >> 2;
    const int tig = lane & 3;
    const int row0 = rowBase + R0 + gid;
    const int row1 = row0 + 8;

    float s0[2] = {0.f, 0.f}, s1[2] = {0.f, 0.f};
    float d0[2] = {0.f, 0.f}, d1[2] = {0.f, 0.f};
#pragma unroll
    for (int t = 0; t < 16; t++) {
        const int col = N0 + t * 8 + tig * 2;
        const int hh = t >> 3;     // 0 or 1 within this warp's 2 heads
        float as0 = __ldg(&att_src[col]), as1 = __ldg(&att_src[col + 1]);
        float ad0 = __ldg(&att_dst[col]), ad1 = __ldg(&att_dst[col + 1]);
        s0[hh] += c[t][0] * as0 + c[t][1] * as1;
        s1[hh] += c[t][2] * as0 + c[t][3] * as1;
        d0[hh] += c[t][0] * ad0 + c[t][1] * ad1;
        d1[hh] += c[t][2] * ad0 + c[t][3] * ad1;
        if (row0 < NN)
            *(float2*)&g_h[(size_t)row0 * HC + col] = make_float2(c[t][0], c[t][1]);
        if (row1 < NN)
            *(float2*)&g_h[(size_t)row1 * HC + col] = make_float2(c[t][2], c[t][3]);
    }
    // reduce over the 4 lanes sharing a row (tig)
#pragma unroll
    for (int hh = 0; hh < 2; hh++) {
        s0[hh] += __shfl_xor_sync(0xffffffffu, s0[hh], 1);
        s0[hh] += __shfl_xor_sync(0xffffffffu, s0[hh], 2);
        s1[hh] += __shfl_xor_sync(0xffffffffu, s1[hh], 1);
        s1[hh] += __shfl_xor_sync(0xffffffffu, s1[hh], 2);
        d0[hh] += __shfl_xor_sync(0xffffffffu, d0[hh], 1);
        d0[hh] += __shfl_xor_sync(0xffffffffu, d0[hh], 2);
        d1[hh] += __shfl_xor_sync(0xffffffffu, d1[hh], 1);
        d1[hh] += __shfl_xor_sync(0xffffffffu, d1[hh], 2);
    }
    if (tig == 0) {
        const int hbase = wc * 2;
#pragma unroll
        for (int hh = 0; hh < 2; hh++) {
            if (row0 < NN) {
                g_asrc[row0 * HEADS + hbase + hh] = s0[hh];
                g_adst[row0 * HEADS + hbase + hh] = d0[hh];
            }
            if (row1 < NN) {
                g_asrc[row1 * HEADS + hbase + hh] = s1[hh];
                g_adst[row1 * HEADS + hbase + hh] = d1[hh];
            }
        }
    }
}

// ---------------- 3) edge pass: denominator accumulation ------------------------
__global__ void edge_kernel(const void* __restrict__ ei)
{
    int e = blockIdx.x * blockDim.x + threadIdx.x;
    if (e >= ET) return;
    int src, dst;
    if (e < NE) {
        src = edge_at(ei, e);
        dst = edge_at(ei, (long long)NE + e);
    } else {
        src = dst = e - NE;
    }
    float4 as = *(const float4*)&g_asrc[src * HEADS];
    float4 ad = *(const float4*)&g_adst[dst * HEADS];
    float4 ex;
    ex.x = __expf(lrelu(as.x + ad.x));
    ex.y = __expf(lrelu(as.y + ad.y));
    ex.z = __expf(lrelu(as.z + ad.z));
    ex.w = __expf(lrelu(as.w + ad.w));
    red_add_v4(&g_den[dst * HEADS], ex);
}

// ---------------- 4) weighted scatter --------------------------------------------
__global__ __launch_bounds__(256) void scatter_kernel(
    const void* __restrict__ ei, float* __restrict__ out)
{
    int gtid = blockIdx.x * blockDim.x + threadIdx.x;
    int e = (gtid >> 5) * 2 + ((gtid & 31) >> 4);
    int j = gtid & 15;
    if (e >= ET) return;
    int src, dst;
    if (e < NE) {
        src = edge_at(ei, e);
        dst = edge_at(ei, (long long)NE + e);
    } else {
        src = dst = e - NE;
    }
    float4 as = *(const float4*)&g_asrc[src * HEADS];
    float4 ad = *(const float4*)&g_adst[dst * HEADS];
    float4 dn = *(const float4*)&g_den[dst * HEADS];
    float a0 = 0.25f * __expf(lrelu(as.x + ad.x)) / dn.x;
    float a1 = 0.25f * __expf(lrelu(as.y + ad.y)) / dn.y;
    float a2 = 0.25f * __expf(lrelu(as.z + ad.z)) / dn.z;
    float a3 = 0.25f * __expf(lrelu(as.w + ad.w)) / dn.w;

    const float4* hp = (const float4*)&g_h[(size_t)src * HC];
    float4 h0 = hp[j];
    float4 h1 = hp[16 + j];
    float4 h2 = hp[32 + j];
    float4 h3 = hp[48 + j];
    float4 v;
    v.x = a0 * h0.x + a1 * h1.x + a2 * h2.x + a3 * h3.x;
    v.y = a0 * h0.y + a1 * h1.y + a2 * h2.y + a3 * h3.y;
    v.z = a0 * h0.z + a1 * h1.z + a2 * h2.z + a3 * h3.z;
    v.w = a0 * h0.w + a1 * h1.w + a2 * h2.w + a3 * h3.w;
    red_add_v4(&out[(size_t)dst * OUTC + 4 * j], v);
}

// ---------------- 5) finalize ------------------------------------------------------
__global__ void final_kernel(float* __restrict__ out, const float* __restrict__ bias)
{
    int i = blockIdx.x * blockDim.x + threadIdx.x;
    if (i >= NN * OUTC) return;
    float v = out[i] + bias[i & (OUTC - 1)];
    out[i] = fmaxf(v, 0.0f);
}

// ---------------- launch --------------------------------------------------------
extern "C" void kernel_launch(void* const* d_in, const int* in_sizes, int n_in,
                              void* d_out, int out_size)
{
    const float* x       = (const float*)d_in[0];
    const void*  ei      = d_in[1];
    const float* W       = (const float*)d_in[2];
    const float* att_src = (const float*)d_in[3];
    const float* att_dst = (const float*)d_in[4];
    const float* bias    = (const float*)d_in[5];
    float* out = (float*)d_out;

    cudaFuncSetAttribute(gemm_tc_kernel,
                         cudaFuncAttributeMaxDynamicSharedMemorySize, GSMEM);

    detect_kernel<<<1, 256>>>((const int*)ei);                        // idx 0
    zero_den_kernel<<<(NN * HEADS + 255) / 256, 256>>>();             // idx 1
    zero_out_kernel<<<(NN * OUTC / 4 + 255) / 256, 256>>>(out);       // idx 2
    gemm_tc_kernel<<<(NN + 127) / 128, 512, GSMEM>>>(x, W, att_src, att_dst); // idx 3
    edge_kernel<<<(ET + 255) / 256, 256>>>(ei);                       // idx 4
    scatter_kernel<<<((size_t)ET * 16 + 255) / 256, 256>>>(ei, out);  // idx 5
    final_kernel<<<(NN * OUTC + 255) / 256, 256>>>(out, bias);        // idx 6
}

// round 11
// speedup vs baseline: 1.4609x; 1.0261x over previous
#include <cuda_runtime.h>
#include <cuda_bf16.h>
#include <math.h>
#include <cstdint>

#define NN 50000
#define NE 800000
#define INC 128
#define OUTC 64
#define HEADS 4
#define HC (HEADS * OUTC)   // 256
#define NEG_SLOPE 0.2f
#define ET (NE + NN)

// ---------------- scratch ------------------------------------------------------
__device__ float g_h[(size_t)NN * HC];
__device__ float g_asrc[NN * HEADS];
__device__ float g_adst[NN * HEADS];
__device__ float g_den[NN * HEADS];
__device__ int   g_is64;

// ---------------- helpers ------------------------------------------------------
__device__ __forceinline__ float lrelu(float v) {
    return v >= 0.0f ? v : NEG_SLOPE * v;
}
__device__ __forceinline__ int edge_at(const void* ei, long long idx) {
    if (g_is64) return (int)((const long long*)ei)[idx];
    return ((const int*)ei)[idx];
}
__device__ __forceinline__ void red_add_v4(float* addr, float4 v) {
    asm volatile("red.global.add.v4.f32 [%0], {%1, %2, %3, %4};"
                 :: "l"(addr), "f"(v.x), "f"(v.y), "f"(v.z), "f"(v.w)
                 : "memory");
}
__device__ __forceinline__ uint32_t smem_to_u32(const void* p) {
    uint32_t a;
    asm("{ .reg .u64 t; cvta.to.shared.u64 t, %1; cvt.u32.u64 %0, t; }"
        : "=r"(a) : "l"(p));
    return a;
}
__device__ __forceinline__ uint32_t pack_bf16x2(float lo, float hi) {
    __nv_bfloat162 p(__float2bfloat16(lo), __float2bfloat16(hi));
    return *(uint32_t*)&p;
}
__device__ __forceinline__ float bf_round(float v) {
    return __bfloat162float(__float2bfloat16(v));
}

#define LDSM_X4(r0, r1, r2, r3, a) \
    asm volatile("ldmatrix.sync.aligned.m8n8.x4.shared.b16 {%0,%1,%2,%3}, [%4];" \
                 : "=r"(r0), "=r"(r1), "=r"(r2), "=r"(r3) : "r"(a))

#define MMA_BF16(c, a0, a1, a2, a3, b0, b1) \
    asm volatile("mma.sync.aligned.m16n8k16.row.col.f32.bf16.bf16.f32 " \
                 "{%0,%1,%2,%3}, {%4,%5,%6,%7}, {%8,%9}, {%0,%1,%2,%3};" \
                 : "+f"((c)[0]), "+f"((c)[1]), "+f"((c)[2]), "+f"((c)[3]) \
                 : "r"(a0), "r"(a1), "r"(a2), "r"(a3), "r"(b0), "r"(b1))

// ---------------- 0) dtype detection -------------------------------------------
__global__ void detect_kernel(const int* __restrict__ ei_raw) {
    __shared__ int nz;
    if (threadIdx.x == 0) nz = 0;
    __syncthreads();
    int local = 0;
    for (int i = threadIdx.x; i < 4096; i += blockDim.x)
        if (ei_raw[2 * i + 1] != 0) local = 1;
    if (local) atomicOr(&nz, 1);
    __syncthreads();
    if (threadIdx.x == 0) g_is64 = (nz == 0) ? 1 : 0;
}

// ---------------- 1) HMMA split-bf16 GEMM + fused attention halves --------------
// CTA 512 thr: tile M=128 x N=256, K chunks of 32. smem stride 40 bf16 (80B).
// h = xh*wh + xh*wl + xl*wh. den-zero folded into prologue.
#define KCH 32
#define STR 40
#define AH_OFF 0
#define AL_OFF 10240
#define BH_OFF 20480
#define BL_OFF 40960
#define GSMEM 61440

__global__ __launch_bounds__(512) void gemm_tc_kernel(
    const float* __restrict__ x, const float* __restrict__ W,
    const float* __restrict__ att_src, const float* __restrict__ att_dst)
{
    // fold den-zero (391 blocks x 512 = 200192 >= NN*HEADS)
    {
        int zi = blockIdx.x * 512 + threadIdx.x;
        if (zi < NN * HEADS) g_den[zi] = 0.0f;
    }

    extern __shared__ char smem[];
    const uint32_t sbase = smem_to_u32(smem);
    const int tid = threadIdx.x;
    const int wid = tid >> 5;
    const int lane = tid & 31;
    const int rowBase = blockIdx.x * 128;

    const int wr = wid & 7;
    const int wc = wid >> 3;
    const int R0 = wr * 16;
    const int N0 = wc * 128;

    const int lrow = lane & 7;
    const int quad = lane >> 3;

    const uint32_t addrA0 = sbase + AH_OFF +
        ((R0 + (quad & 1) * 8 + lrow) * STR + (quad >> 1) * 8) * 2;
    const uint32_t addrB0 = sbase + BH_OFF +
        ((N0 + (quad >> 1) * 8 + lrow) * STR + (quad & 1) * 8) * 2;

    float c[16][4];
#pragma unroll
    for (int t = 0; t < 16; t++)
#pragma unroll
        for (int q = 0; q < 4; q++) c[t][q] = 0.0f;

    const int xrow = tid >> 2;
    const int xkp = (tid & 3) * 8;
    const int wrow = tid >> 1;
    const int wkp = (tid & 1) * 16;

    for (int kc = 0; kc < 4; kc++) {
        const int k0 = kc * KCH;
        {
            int gr = rowBase + xrow;
            float4 v0 = make_float4(0.f, 0.f, 0.f, 0.f), v1 = v0;
            if (gr < NN) {
                const float4* xp = (const float4*)(x + (size_t)gr * INC + k0 + xkp);
                v0 = __ldg(&xp[0]);
                v1 = __ldg(&xp[1]);
            }
            float f[8] = {v0.x, v0.y, v0.z, v0.w, v1.x, v1.y, v1.z, v1.w};
            uint32_t* ah = (uint32_t*)(smem + AH_OFF + (xrow * STR + xkp) * 2);
            uint32_t* al = (uint32_t*)(smem + AL_OFF + (xrow * STR + xkp) * 2);
#pragma unroll
            for (int j = 0; j < 4; j++) {
                float a = f[2 * j], b = f[2 * j + 1];
                ah[j] = pack_bf16x2(a, b);
                al[j] = pack_bf16x2(a - bf_round(a), b - bf_round(b));
            }
        }
        {
            const float4* wp = (const float4*)(W + (size_t)wrow * INC + k0 + wkp);
            float4 v0 = __ldg(&wp[0]);
            float4 v1 = __ldg(&wp[1]);
            float4 v2 = __ldg(&wp[2]);
            float4 v3 = __ldg(&wp[3]);
            float f[16] = {v0.x, v0.y, v0.z, v0.w, v1.x, v1.y, v1.z, v1.w,
                           v2.x, v2.y, v2.z, v2.w, v3.x, v3.y, v3.z, v3.w};
            uint32_t* bh = (uint32_t*)(smem + BH_OFF + (wrow * STR + wkp) * 2);
            uint32_t* bl = (uint32_t*)(smem + BL_OFF + (wrow * STR + wkp) * 2);
#pragma unroll
            for (int j = 0; j < 8; j++) {
                float a = f[2 * j], b = f[2 * j + 1];
                bh[j] = pack_bf16x2(a, b);
                bl[j] = pack_bf16x2(a - bf_round(a), b - bf_round(b));
            }
        }
        __syncthreads();

#pragma unroll
        for (int ks = 0; ks < 2; ks++) {
            const uint32_t aAH = addrA0 + ks * 32;
            uint32_t ah0, ah1, ah2, ah3, al0, al1, al2, al3;
            LDSM_X4(ah0, ah1, ah2, ah3, aAH);
            LDSM_X4(al0, al1, al2, al3, aAH + AL_OFF);

            uint32_t aB = addrB0 + ks * 32;
#pragma unroll
            for (int tp = 0; tp < 8; tp++) {
                uint32_t bh0, bh1, bh2, bh3, bl0, bl1, bl2, bl3;
                LDSM_X4(bh0, bh1, bh2, bh3, aB);
                LDSM_X4(bl0, bl1, bl2, bl3, aB + 20480);
                const int t = tp * 2;
                MMA_BF16(c[t],     ah0, ah1, ah2, ah3, bh0, bh1);
                MMA_BF16(c[t],     ah0, ah1, ah2, ah3, bl0, bl1);
                MMA_BF16(c[t],     al0, al1, al2, al3, bh0, bh1);
                MMA_BF16(c[t + 1], ah0, ah1, ah2, ah3, bh2, bh3);
                MMA_BF16(c[t + 1], ah0, ah1, ah2, ah3, bl2, bl3);
                MMA_BF16(c[t + 1], al0, al1, al2, al3, bh2, bh3);
                aB += 16 * STR * 2;
            }
        }
        __syncthreads();
    }

    const int gid = lane >> 2;
    const int tig = lane & 3;
    const int row0 = rowBase + R0 + gid;
    const int row1 = row0 + 8;

    float s0[2] = {0.f, 0.f}, s1[2] = {0.f, 0.f};
    float d0[2] = {0.f, 0.f}, d1[2] = {0.f, 0.f};
#pragma unroll
    for (int t = 0; t < 16; t++) {
        const int col = N0 + t * 8 + tig * 2;
        const int hh = t >> 3;
        float as0 = __ldg(&att_src[col]), as1 = __ldg(&att_src[col + 1]);
        float ad0 = __ldg(&att_dst[col]), ad1 = __ldg(&att_dst[col + 1]);
        s0[hh] += c[t][0] * as0 + c[t][1] * as1;
        s1[hh] += c[t][2] * as0 + c[t][3] * as1;
        d0[hh] += c[t][0] * ad0 + c[t][1] * ad1;
        d1[hh] += c[t][2] * ad0 + c[t][3] * ad1;
        if (row0 < NN)
            *(float2*)&g_h[(size_t)row0 * HC + col] = make_float2(c[t][0], c[t][1]);
        if (row1 < NN)
            *(float2*)&g_h[(size_t)row1 * HC + col] = make_float2(c[t][2], c[t][3]);
    }
#pragma unroll
    for (int hh = 0; hh < 2; hh++) {
        s0[hh] += __shfl_xor_sync(0xffffffffu, s0[hh], 1);
        s0[hh] += __shfl_xor_sync(0xffffffffu, s0[hh], 2);
        s1[hh] += __shfl_xor_sync(0xffffffffu, s1[hh], 1);
        s1[hh] += __shfl_xor_sync(0xffffffffu, s1[hh], 2);
        d0[hh] += __shfl_xor_sync(0xffffffffu, d0[hh], 1);
        d0[hh] += __shfl_xor_sync(0xffffffffu, d0[hh], 2);
        d1[hh] += __shfl_xor_sync(0xffffffffu, d1[hh], 1);
        d1[hh] += __shfl_xor_sync(0xffffffffu, d1[hh], 2);
    }
    if (tig == 0) {
        const int hbase = wc * 2;
#pragma unroll
        for (int hh = 0; hh < 2; hh++) {
            if (row0 < NN) {
                g_asrc[row0 * HEADS + hbase + hh] = s0[hh];
                g_adst[row0 * HEADS + hbase + hh] = d0[hh];
            }
            if (row1 < NN) {
                g_asrc[row1 * HEADS + hbase + hh] = s1[hh];
                g_adst[row1 * HEADS + hbase + hh] = d1[hh];
            }
        }
    }
}

// ---------------- 2) edge pass: denominator accumulation + out zero -------------
__global__ void edge_kernel(const void* __restrict__ ei, float* __restrict__ out)
{
    int e = blockIdx.x * blockDim.x + threadIdx.x;
    if (e < NN * OUTC / 4)
        ((float4*)out)[e] = make_float4(0.f, 0.f, 0.f, 0.f);
    if (e >= ET) return;
    int src, dst;
    if (e < NE) {
        src = edge_at(ei, e);
        dst = edge_at(ei, (long long)NE + e);
    } else {
        src = dst = e - NE;
    }
    float4 as = *(const float4*)&g_asrc[src * HEADS];
    float4 ad = *(const float4*)&g_adst[dst * HEADS];
    float4 ex;
    ex.x = __expf(lrelu(as.x + ad.x));
    ex.y = __expf(lrelu(as.y + ad.y));
    ex.z = __expf(lrelu(as.z + ad.z));
    ex.w = __expf(lrelu(as.w + ad.w));
    red_add_v4(&g_den[dst * HEADS], ex);
}

// ---------------- 3) weighted scatter: lane0-per-edge alpha + broadcast ----------
__global__ __launch_bounds__(256) void scatter_kernel(
    const void* __restrict__ ei, float* __restrict__ out)
{
    const int gtid = blockIdx.x * blockDim.x + threadIdx.x;
    const int warp = gtid >> 5;
    const int lane = threadIdx.x & 31;
    const int eh = lane >> 4;
    const int j = lane & 15;
    const long long e = (long long)warp * 2 + eh;
    const bool valid = (e < ET);
    const long long ec = valid ? e : (ET - 1);

    int src = 0, dst = 0;
    float a0 = 0.f, a1 = 0.f, a2 = 0.f, a3 = 0.f;
    if (j == 0) {
        if (ec < NE) {
            src = edge_at(ei, ec);
            dst = edge_at(ei, (long long)NE + ec);
        } else {
            src = dst = (int)(ec - NE);
        }
        float4 as = *(const float4*)&g_asrc[src * HEADS];
        float4 ad = *(const float4*)&g_adst[dst * HEADS];
        float4 dn = *(const float4*)&g_den[dst * HEADS];
        a0 = 0.25f * __fdividef(__expf(lrelu(as.x + ad.x)), dn.x);
        a1 = 0.25f * __fdividef(__expf(lrelu(as.y + ad.y)), dn.y);
        a2 = 0.25f * __fdividef(__expf(lrelu(as.z + ad.z)), dn.z);
        a3 = 0.25f * __fdividef(__expf(lrelu(as.w + ad.w)), dn.w);
    }
    const int lsrc = eh << 4;   // lane 0 or 16
    src = __shfl_sync(0xffffffffu, src, lsrc);
    dst = __shfl_sync(0xffffffffu, dst, lsrc);
    a0 = __shfl_sync(0xffffffffu, a0, lsrc);
    a1 = __shfl_sync(0xffffffffu, a1, lsrc);
    a2 = __shfl_sync(0xffffffffu, a2, lsrc);
    a3 = __shfl_sync(0xffffffffu, a3, lsrc);

    const float4* hp = (const float4*)&g_h[(size_t)src * HC];
    float4 h0 = hp[j];
    float4 h1 = hp[16 + j];
    float4 h2 = hp[32 + j];
    float4 h3 = hp[48 + j];
    float4 v;
    v.x = a0 * h0.x + a1 * h1.x + a2 * h2.x + a3 * h3.x;
    v.y = a0 * h0.y + a1 * h1.y + a2 * h2.y + a3 * h3.y;
    v.z = a0 * h0.z + a1 * h1.z + a2 * h2.z + a3 * h3.z;
    v.w = a0 * h0.w + a1 * h1.w + a2 * h2.w + a3 * h3.w;
    if (valid) red_add_v4(&out[(size_t)dst * OUTC + 4 * j], v);
}

// ---------------- 4) finalize ------------------------------------------------------
__global__ void final_kernel(float* __restrict__ out, const float* __restrict__ bias)
{
    int i = blockIdx.x * blockDim.x + threadIdx.x;
    if (i >= NN * OUTC) return;
    float v = out[i] + bias[i & (OUTC - 1)];
    out[i] = fmaxf(v, 0.0f);
}

// ---------------- launch --------------------------------------------------------
extern "C" void kernel_launch(void* const* d_in, const int* in_sizes, int n_in,
                              void* d_out, int out_size)
{
    const float* x       = (const float*)d_in[0];
    const void*  ei      = d_in[1];
    const float* W       = (const float*)d_in[2];
    const float* att_src = (const float*)d_in[3];
    const float* att_dst = (const float*)d_in[4];
    const float* bias    = (const float*)d_in[5];
    float* out = (float*)d_out;

    cudaFuncSetAttribute(gemm_tc_kernel,
                         cudaFuncAttributeMaxDynamicSharedMemorySize, GSMEM);

    gemm_tc_kernel<<<(NN + 127) / 128, 512, GSMEM>>>(x, W, att_src, att_dst); // idx 0
    detect_kernel<<<1, 256>>>((const int*)ei);                        // idx 1
    edge_kernel<<<(ET + 255) / 256, 256>>>(ei, out);                  // idx 2
    scatter_kernel<<<((size_t)ET * 16 + 255) / 256, 256>>>(ei, out);  // idx 3 (profiled)
    final_kernel<<<(NN * OUTC + 255) / 256, 256>>>(out, bias);        // idx 4
}

// round 12
// speedup vs baseline: 1.5663x; 1.0721x over previous
#include <cuda_runtime.h>
#include <cuda_bf16.h>
#include <cuda_fp16.h>
#include <math.h>
#include <cstdint>

#define NN 50000
#define NE 800000
#define INC 128
#define OUTC 64
#define HEADS 4
#define HC (HEADS * OUTC)   // 256
#define NEG_SLOPE 0.2f
#define ET (NE + NN)

// ---------------- scratch ------------------------------------------------------
__device__ __half g_hh[(size_t)NN * HC];    // projected features, fp16
__device__ float g_asrc[NN * HEADS];
__device__ float g_adst[NN * HEADS];
__device__ float g_den[NN * HEADS];
__device__ int   g_is64;

// ---------------- helpers ------------------------------------------------------
__device__ __forceinline__ float lrelu(float v) {
    return v >= 0.0f ? v : NEG_SLOPE * v;
}
__device__ __forceinline__ int edge_at(const void* ei, long long idx) {
    if (g_is64) return (int)((const long long*)ei)[idx];
    return ((const int*)ei)[idx];
}
__device__ __forceinline__ void red_add_v4(float* addr, float4 v) {
    asm volatile("red.global.add.v4.f32 [%0], {%1, %2, %3, %4};"
                 :: "l"(addr), "f"(v.x), "f"(v.y), "f"(v.z), "f"(v.w)
                 : "memory");
}
__device__ __forceinline__ uint32_t smem_to_u32(const void* p) {
    uint32_t a;
    asm("{ .reg .u64 t; cvta.to.shared.u64 t, %1; cvt.u32.u64 %0, t; }"
        : "=r"(a) : "l"(p));
    return a;
}
__device__ __forceinline__ uint32_t pack_bf16x2(float lo, float hi) {
    __nv_bfloat162 p(__float2bfloat16(lo), __float2bfloat16(hi));
    return *(uint32_t*)&p;
}
__device__ __forceinline__ float bf_round(float v) {
    return __bfloat162float(__float2bfloat16(v));
}

#define LDSM_X4(r0, r1, r2, r3, a) \
    asm volatile("ldmatrix.sync.aligned.m8n8.x4.shared.b16 {%0,%1,%2,%3}, [%4];" \
                 : "=r"(r0), "=r"(r1), "=r"(r2), "=r"(r3) : "r"(a))

#define MMA_BF16(c, a0, a1, a2, a3, b0, b1) \
    asm volatile("mma.sync.aligned.m16n8k16.row.col.f32.bf16.bf16.f32 " \
                 "{%0,%1,%2,%3}, {%4,%5,%6,%7}, {%8,%9}, {%0,%1,%2,%3};" \
                 : "+f"((c)[0]), "+f"((c)[1]), "+f"((c)[2]), "+f"((c)[3]) \
                 : "r"(a0), "r"(a1), "r"(a2), "r"(a3), "r"(b0), "r"(b1))

// ---------------- 0) dtype detection -------------------------------------------
__global__ void detect_kernel(const int* __restrict__ ei_raw) {
    __shared__ int nz;
    if (threadIdx.x == 0) nz = 0;
    __syncthreads();
    int local = 0;
    for (int i = threadIdx.x; i < 4096; i += blockDim.x)
        if (ei_raw[2 * i + 1] != 0) local = 1;
    if (local) atomicOr(&nz, 1);
    __syncthreads();
    if (threadIdx.x == 0) g_is64 = (nz == 0) ? 1 : 0;
}

// ---------------- 1) HMMA split-bf16 GEMM + fused attention halves --------------
// CTA 512 thr: tile M=128 x N=256, K chunks of 32. smem stride 40 bf16 (80B).
// h = xh*wh + xh*wl + xl*wh, stored as fp16. den-zero folded into prologue.
#define KCH 32
#define STR 40
#define AH_OFF 0
#define AL_OFF 10240
#define BH_OFF 20480
#define BL_OFF 40960
#define GSMEM 61440

__global__ __launch_bounds__(512) void gemm_tc_kernel(
    const float* __restrict__ x, const float* __restrict__ W,
    const float* __restrict__ att_src, const float* __restrict__ att_dst)
{
    {
        int zi = blockIdx.x * 512 + threadIdx.x;
        if (zi < NN * HEADS) g_den[zi] = 0.0f;
    }

    extern __shared__ char smem[];
    const uint32_t sbase = smem_to_u32(smem);
    const int tid = threadIdx.x;
    const int wid = tid >> 5;
    const int lane = tid & 31;
    const int rowBase = blockIdx.x * 128;

    const int wr = wid & 7;
    const int wc = wid >> 3;
    const int R0 = wr * 16;
    const int N0 = wc * 128;

    const int lrow = lane & 7;
    const int quad = lane >> 3;

    const uint32_t addrA0 = sbase + AH_OFF +
        ((R0 + (quad & 1) * 8 + lrow) * STR + (quad >> 1) * 8) * 2;
    const uint32_t addrB0 = sbase + BH_OFF +
        ((N0 + (quad >> 1) * 8 + lrow) * STR + (quad & 1) * 8) * 2;

    float c[16][4];
#pragma unroll
    for (int t = 0; t < 16; t++)
#pragma unroll
        for (int q = 0; q < 4; q++) c[t][q] = 0.0f;

    const int xrow = tid >> 2;
    const int xkp = (tid & 3) * 8;
    const int wrow = tid >> 1;
    const int wkp = (tid & 1) * 16;

    for (int kc = 0; kc < 4; kc++) {
        const int k0 = kc * KCH;
        {
            int gr = rowBase + xrow;
            float4 v0 = make_float4(0.f, 0.f, 0.f, 0.f), v1 = v0;
            if (gr < NN) {
                const float4* xp = (const float4*)(x + (size_t)gr * INC + k0 + xkp);
                v0 = __ldg(&xp[0]);
                v1 = __ldg(&xp[1]);
            }
            float f[8] = {v0.x, v0.y, v0.z, v0.w, v1.x, v1.y, v1.z, v1.w};
            uint32_t* ah = (uint32_t*)(smem + AH_OFF + (xrow * STR + xkp) * 2);
            uint32_t* al = (uint32_t*)(smem + AL_OFF + (xrow * STR + xkp) * 2);
#pragma unroll
            for (int j = 0; j < 4; j++) {
                float a = f[2 * j], b = f[2 * j + 1];
                ah[j] = pack_bf16x2(a, b);
                al[j] = pack_bf16x2(a - bf_round(a), b - bf_round(b));
            }
        }
        {
            const float4* wp = (const float4*)(W + (size_t)wrow * INC + k0 + wkp);
            float4 v0 = __ldg(&wp[0]);
            float4 v1 = __ldg(&wp[1]);
            float4 v2 = __ldg(&wp[2]);
            float4 v3 = __ldg(&wp[3]);
            float f[16] = {v0.x, v0.y, v0.z, v0.w, v1.x, v1.y, v1.z, v1.w,
                           v2.x, v2.y, v2.z, v2.w, v3.x, v3.y, v3.z, v3.w};
            uint32_t* bh = (uint32_t*)(smem + BH_OFF + (wrow * STR + wkp) * 2);
            uint32_t* bl = (uint32_t*)(smem + BL_OFF + (wrow * STR + wkp) * 2);
#pragma unroll
            for (int j = 0; j < 8; j++) {
                float a = f[2 * j], b = f[2 * j + 1];
                bh[j] = pack_bf16x2(a, b);
                bl[j] = pack_bf16x2(a - bf_round(a), b - bf_round(b));
            }
        }
        __syncthreads();

#pragma unroll
        for (int ks = 0; ks < 2; ks++) {
            const uint32_t aAH = addrA0 + ks * 32;
            uint32_t ah0, ah1, ah2, ah3, al0, al1, al2, al3;
            LDSM_X4(ah0, ah1, ah2, ah3, aAH);
            LDSM_X4(al0, al1, al2, al3, aAH + AL_OFF);

            uint32_t aB = addrB0 + ks * 32;
#pragma unroll
            for (int tp = 0; tp < 8; tp++) {
                uint32_t bh0, bh1, bh2, bh3, bl0, bl1, bl2, bl3;
                LDSM_X4(bh0, bh1, bh2, bh3, aB);
                LDSM_X4(bl0, bl1, bl2, bl3, aB + 20480);
                const int t = tp * 2;
                MMA_BF16(c[t],     ah0, ah1, ah2, ah3, bh0, bh1);
                MMA_BF16(c[t],     ah0, ah1, ah2, ah3, bl0, bl1);
                MMA_BF16(c[t],     al0, al1, al2, al3, bh0, bh1);
                MMA_BF16(c[t + 1], ah0, ah1, ah2, ah3, bh2, bh3);
                MMA_BF16(c[t + 1], ah0, ah1, ah2, ah3, bl2, bl3);
                MMA_BF16(c[t + 1], al0, al1, al2, al3, bh2, bh3);
                aB += 16 * STR * 2;
            }
        }
        __syncthreads();
    }

    const int gid = lane >> 2;
    const int tig = lane & 3;
    const int row0 = rowBase + R0 + gid;
    const int row1 = row0 + 8;

    float s0[2] = {0.f, 0.f}, s1[2] = {0.f, 0.f};
    float d0[2] = {0.f, 0.f}, d1[2] = {0.f, 0.f};
#pragma unroll
    for (int t = 0; t < 16; t++) {
        const int col = N0 + t * 8 + tig * 2;
        const int hh = t >> 3;
        float as0 = __ldg(&att_src[col]), as1 = __ldg(&att_src[col + 1]);
        float ad0 = __ldg(&att_dst[col]), ad1 = __ldg(&att_dst[col + 1]);
        s0[hh] += c[t][0] * as0 + c[t][1] * as1;
        s1[hh] += c[t][2] * as0 + c[t][3] * as1;
        d0[hh] += c[t][0] * ad0 + c[t][1] * ad1;
        d1[hh] += c[t][2] * ad0 + c[t][3] * ad1;
        if (row0 < NN) {
            __half2 p = __floats2half2_rn(c[t][0], c[t][1]);
            *(__half2*)&g_hh[(size_t)row0 * HC + col] = p;
        }
        if (row1 < NN) {
            __half2 p = __floats2half2_rn(c[t][2], c[t][3]);
            *(__half2*)&g_hh[(size_t)row1 * HC + col] = p;
        }
    }
#pragma unroll
    for (int hh = 0; hh < 2; hh++) {
        s0[hh] += __shfl_xor_sync(0xffffffffu, s0[hh], 1);
        s0[hh] += __shfl_xor_sync(0xffffffffu, s0[hh], 2);
        s1[hh] += __shfl_xor_sync(0xffffffffu, s1[hh], 1);
        s1[hh] += __shfl_xor_sync(0xffffffffu, s1[hh], 2);
        d0[hh] += __shfl_xor_sync(0xffffffffu, d0[hh], 1);
        d0[hh] += __shfl_xor_sync(0xffffffffu, d0[hh], 2);
        d1[hh] += __shfl_xor_sync(0xffffffffu, d1[hh], 1);
        d1[hh] += __shfl_xor_sync(0xffffffffu, d1[hh], 2);
    }
    if (tig == 0) {
        const int hbase = wc * 2;
#pragma unroll
        for (int hh = 0; hh < 2; hh++) {
            if (row0 < NN) {
                g_asrc[row0 * HEADS + hbase + hh] = s0[hh];
                g_adst[row0 * HEADS + hbase + hh] = d0[hh];
            }
            if (row1 < NN) {
                g_asrc[row1 * HEADS + hbase + hh] = s1[hh];
                g_adst[row1 * HEADS + hbase + hh] = d1[hh];
            }
        }
    }
}

// ---------------- 2) edge pass: denominator accumulation + out zero -------------
__global__ void edge_kernel(const void* __restrict__ ei, float* __restrict__ out)
{
    int e = blockIdx.x * blockDim.x + threadIdx.x;
    if (e < NN * OUTC / 4)
        ((float4*)out)[e] = make_float4(0.f, 0.f, 0.f, 0.f);
    if (e >= ET) return;
    int src, dst;
    if (e < NE) {
        src = edge_at(ei, e);
        dst = edge_at(ei, (long long)NE + e);
    } else {
        src = dst = e - NE;
    }
    float4 as = *(const float4*)&g_asrc[src * HEADS];
    float4 ad = *(const float4*)&g_adst[dst * HEADS];
    float4 ex;
    ex.x = __expf(lrelu(as.x + ad.x));
    ex.y = __expf(lrelu(as.y + ad.y));
    ex.z = __expf(lrelu(as.z + ad.z));
    ex.w = __expf(lrelu(as.w + ad.w));
    red_add_v4(&g_den[dst * HEADS], ex);
}

// ---------------- 3) weighted scatter: fp16 h, lane0 alpha + broadcast ----------
__global__ __launch_bounds__(256) void scatter_kernel(
    const void* __restrict__ ei, float* __restrict__ out)
{
    const int gtid = blockIdx.x * blockDim.x + threadIdx.x;
    const int warp = gtid >> 5;
    const int lane = threadIdx.x & 31;
    const int eh = lane >> 4;
    const int j = lane & 15;
    const long long e = (long long)warp * 2 + eh;
    const bool valid = (e < ET);
    const long long ec = valid ? e : (ET - 1);

    int src = 0, dst = 0;
    float a0 = 0.f, a1 = 0.f, a2 = 0.f, a3 = 0.f;
    if (j == 0) {
        if (ec < NE) {
            src = edge_at(ei, ec);
            dst = edge_at(ei, (long long)NE + ec);
        } else {
            src = dst = (int)(ec - NE);
        }
        float4 as = *(const float4*)&g_asrc[src * HEADS];
        float4 ad = *(const float4*)&g_adst[dst * HEADS];
        float4 dn = *(const float4*)&g_den[dst * HEADS];
        a0 = 0.25f * __fdividef(__expf(lrelu(as.x + ad.x)), dn.x);
        a1 = 0.25f * __fdividef(__expf(lrelu(as.y + ad.y)), dn.y);
        a2 = 0.25f * __fdividef(__expf(lrelu(as.z + ad.z)), dn.z);
        a3 = 0.25f * __fdividef(__expf(lrelu(as.w + ad.w)), dn.w);
    }
    const int lsrc = eh << 4;
    src = __shfl_sync(0xffffffffu, src, lsrc);
    dst = __shfl_sync(0xffffffffu, dst, lsrc);
    a0 = __shfl_sync(0xffffffffu, a0, lsrc);
    a1 = __shfl_sync(0xffffffffu, a1, lsrc);
    a2 = __shfl_sync(0xffffffffu, a2, lsrc);
    a3 = __shfl_sync(0xffffffffu, a3, lsrc);

    // fp16 h: row = 64 uint2 (16 per head); lane j reads channels 4j..4j+3 per head
    const uint2* h2 = (const uint2*)(g_hh + (size_t)src * HC);
    uint2 u0 = h2[j];
    uint2 u1 = h2[16 + j];
    uint2 u2 = h2[32 + j];
    uint2 u3 = h2[48 + j];
    float2 p00 = __half22float2(*(const __half2*)&u0.x);
    float2 p01 = __half22float2(*(const __half2*)&u0.y);
    float2 p10 = __half22float2(*(const __half2*)&u1.x);
    float2 p11 = __half22float2(*(const __half2*)&u1.y);
    float2 p20 = __half22float2(*(const __half2*)&u2.x);
    float2 p21 = __half22float2(*(const __half2*)&u2.y);
    float2 p30 = __half22float2(*(const __half2*)&u3.x);
    float2 p31 = __half22float2(*(const __half2*)&u3.y);

    float4 v;
    v.x = a0 * p00.x + a1 * p10.x + a2 * p20.x + a3 * p30.x;
    v.y = a0 * p00.y + a1 * p10.y + a2 * p20.y + a3 * p30.y;
    v.z = a0 * p01.x + a1 * p11.x + a2 * p21.x + a3 * p31.x;
    v.w = a0 * p01.y + a1 * p11.y + a2 * p21.y + a3 * p31.y;
    if (valid) red_add_v4(&out[(size_t)dst * OUTC + 4 * j], v);
}

// ---------------- 4) finalize ------------------------------------------------------
__global__ void final_kernel(float* __restrict__ out, const float* __restrict__ bias)
{
    int i = blockIdx.x * blockDim.x + threadIdx.x;
    if (i >= NN * OUTC) return;
    float v = out[i] + bias[i & (OUTC - 1)];
    out[i] = fmaxf(v, 0.0f);
}

// ---------------- launch --------------------------------------------------------
extern "C" void kernel_launch(void* const* d_in, const int* in_sizes, int n_in,
                              void* d_out, int out_size)
{
    const float* x       = (const float*)d_in[0];
    const void*  ei      = d_in[1];
    const float* W       = (const float*)d_in[2];
    const float* att_src = (const float*)d_in[3];
    const float* att_dst = (const float*)d_in[4];
    const float* bias    = (const float*)d_in[5];
    float* out = (float*)d_out;

    cudaFuncSetAttribute(gemm_tc_kernel,
                         cudaFuncAttributeMaxDynamicSharedMemorySize, GSMEM);

    gemm_tc_kernel<<<(NN + 127) / 128, 512, GSMEM>>>(x, W, att_src, att_dst); // idx 0
    detect_kernel<<<1, 256>>>((const int*)ei);                        // idx 1
    edge_kernel<<<(ET + 255) / 256, 256>>>(ei, out);                  // idx 2
    scatter_kernel<<<((size_t)ET * 16 + 255) / 256, 256>>>(ei, out);  // idx 3 (profiled)
    final_kernel<<<(NN * OUTC + 255) / 256, 256>>>(out, bias);        // idx 4
}

// round 13
// speedup vs baseline: 1.5693x; 1.0020x over previous
#include <cuda_runtime.h>
#include <cuda_bf16.h>
#include <cuda_fp16.h>
#include <math.h>
#include <cstdint>

#define NN 50000
#define NE 800000
#define INC 128
#define OUTC 64
#define HEADS 4
#define HC (HEADS * OUTC)   // 256
#define NEG_SLOPE 0.2f
#define ET (NE + NN)

// ---------------- scratch ------------------------------------------------------
__device__ __half g_hh[(size_t)NN * HC];    // projected features, fp16
__device__ float g_asrc[NN * HEADS];
__device__ float g_adst[NN * HEADS];
__device__ float g_den[NN * HEADS];
__device__ int   g_is64;

// ---------------- helpers ------------------------------------------------------
__device__ __forceinline__ float lrelu(float v) {
    return v >= 0.0f ? v : NEG_SLOPE * v;
}
__device__ __forceinline__ int edge_at(const void* ei, long long idx) {
    if (g_is64) return (int)((const long long*)ei)[idx];
    return ((const int*)ei)[idx];
}
__device__ __forceinline__ void red_add_v4(float* addr, float4 v) {
    asm volatile("red.global.add.v4.f32 [%0], {%1, %2, %3, %4};"
                 :: "l"(addr), "f"(v.x), "f"(v.y), "f"(v.z), "f"(v.w)
                 : "memory");
}
__device__ __forceinline__ uint32_t smem_to_u32(const void* p) {
    uint32_t a;
    asm("{ .reg .u64 t; cvta.to.shared.u64 t, %1; cvt.u32.u64 %0, t; }"
        : "=r"(a) : "l"(p));
    return a;
}
__device__ __forceinline__ uint32_t pack_bf16x2(float lo, float hi) {
    __nv_bfloat162 p(__float2bfloat16(lo), __float2bfloat16(hi));
    return *(uint32_t*)&p;
}
__device__ __forceinline__ float bf_round(float v) {
    return __bfloat162float(__float2bfloat16(v));
}

#define LDSM_X4(r0, r1, r2, r3, a) \
    asm volatile("ldmatrix.sync.aligned.m8n8.x4.shared.b16 {%0,%1,%2,%3}, [%4];" \
                 : "=r"(r0), "=r"(r1), "=r"(r2), "=r"(r3) : "r"(a))

#define MMA_BF16(c, a0, a1, a2, a3, b0, b1) \
    asm volatile("mma.sync.aligned.m16n8k16.row.col.f32.bf16.bf16.f32 " \
                 "{%0,%1,%2,%3}, {%4,%5,%6,%7}, {%8,%9}, {%0,%1,%2,%3};" \
                 : "+f"((c)[0]), "+f"((c)[1]), "+f"((c)[2]), "+f"((c)[3]) \
                 : "r"(a0), "r"(a1), "r"(a2), "r"(a3), "r"(b0), "r"(b1))

// ---------------- 0) dtype detection -------------------------------------------
__global__ void detect_kernel(const int* __restrict__ ei_raw) {
    __shared__ int nz;
    if (threadIdx.x == 0) nz = 0;
    __syncthreads();
    int local = 0;
    for (int i = threadIdx.x; i < 4096; i += blockDim.x)
        if (ei_raw[2 * i + 1] != 0) local = 1;
    if (local) atomicOr(&nz, 1);
    __syncthreads();
    if (threadIdx.x == 0) g_is64 = (nz == 0) ? 1 : 0;
}

// ---------------- 1) HMMA split-bf16 GEMM + fused attention halves --------------
#define KCH 32
#define STR 40
#define AH_OFF 0
#define AL_OFF 10240
#define BH_OFF 20480
#define BL_OFF 40960
#define GSMEM 61440

__global__ __launch_bounds__(512) void gemm_tc_kernel(
    const float* __restrict__ x, const float* __restrict__ W,
    const float* __restrict__ att_src, const float* __restrict__ att_dst)
{
    {
        int zi = blockIdx.x * 512 + threadIdx.x;
        if (zi < NN * HEADS) g_den[zi] = 0.0f;
    }

    extern __shared__ char smem[];
    const uint32_t sbase = smem_to_u32(smem);
    const int tid = threadIdx.x;
    const int wid = tid >> 5;
    const int lane = tid & 31;
    const int rowBase = blockIdx.x * 128;

    const int wr = wid & 7;
    const int wc = wid >> 3;
    const int R0 = wr * 16;
    const int N0 = wc * 128;

    const int lrow = lane & 7;
    const int quad = lane >> 3;

    const uint32_t addrA0 = sbase + AH_OFF +
        ((R0 + (quad & 1) * 8 + lrow) * STR + (quad >> 1) * 8) * 2;
    const uint32_t addrB0 = sbase + BH_OFF +
        ((N0 + (quad >> 1) * 8 + lrow) * STR + (quad & 1) * 8) * 2;

    float c[16][4];
#pragma unroll
    for (int t = 0; t < 16; t++)
#pragma unroll
        for (int q = 0; q < 4; q++) c[t][q] = 0.0f;

    const int xrow = tid >> 2;
    const int xkp = (tid & 3) * 8;
    const int wrow = tid >> 1;
    const int wkp = (tid & 1) * 16;

    for (int kc = 0; kc < 4; kc++) {
        const int k0 = kc * KCH;
        {
            int gr = rowBase + xrow;
            float4 v0 = make_float4(0.f, 0.f, 0.f, 0.f), v1 = v0;
            if (gr < NN) {
                const float4* xp = (const float4*)(x + (size_t)gr * INC + k0 + xkp);
                v0 = __ldg(&xp[0]);
                v1 = __ldg(&xp[1]);
            }
            float f[8] = {v0.x, v0.y, v0.z, v0.w, v1.x, v1.y, v1.z, v1.w};
            uint32_t* ah = (uint32_t*)(smem + AH_OFF + (xrow * STR + xkp) * 2);
            uint32_t* al = (uint32_t*)(smem + AL_OFF + (xrow * STR + xkp) * 2);
#pragma unroll
            for (int j = 0; j < 4; j++) {
                float a = f[2 * j], b = f[2 * j + 1];
                ah[j] = pack_bf16x2(a, b);
                al[j] = pack_bf16x2(a - bf_round(a), b - bf_round(b));
            }
        }
        {
            const float4* wp = (const float4*)(W + (size_t)wrow * INC + k0 + wkp);
            float4 v0 = __ldg(&wp[0]);
            float4 v1 = __ldg(&wp[1]);
            float4 v2 = __ldg(&wp[2]);
            float4 v3 = __ldg(&wp[3]);
            float f[16] = {v0.x, v0.y, v0.z, v0.w, v1.x, v1.y, v1.z, v1.w,
                           v2.x, v2.y, v2.z, v2.w, v3.x, v3.y, v3.z, v3.w};
            uint32_t* bh = (uint32_t*)(smem + BH_OFF + (wrow * STR + wkp) * 2);
            uint32_t* bl = (uint32_t*)(smem + BL_OFF + (wrow * STR + wkp) * 2);
#pragma unroll
            for (int j = 0; j < 8; j++) {
                float a = f[2 * j], b = f[2 * j + 1];
                bh[j] = pack_bf16x2(a, b);
                bl[j] = pack_bf16x2(a - bf_round(a), b - bf_round(b));
            }
        }
        __syncthreads();

#pragma unroll
        for (int ks = 0; ks < 2; ks++) {
            const uint32_t aAH = addrA0 + ks * 32;
            uint32_t ah0, ah1, ah2, ah3, al0, al1, al2, al3;
            LDSM_X4(ah0, ah1, ah2, ah3, aAH);
            LDSM_X4(al0, al1, al2, al3, aAH + AL_OFF);

            uint32_t aB = addrB0 + ks * 32;
#pragma unroll
            for (int tp = 0; tp < 8; tp++) {
                uint32_t bh0, bh1, bh2, bh3, bl0, bl1, bl2, bl3;
                LDSM_X4(bh0, bh1, bh2, bh3, aB);
                LDSM_X4(bl0, bl1, bl2, bl3, aB + 20480);
                const int t = tp * 2;
                MMA_BF16(c[t],     ah0, ah1, ah2, ah3, bh0, bh1);
                MMA_BF16(c[t],     ah0, ah1, ah2, ah3, bl0, bl1);
                MMA_BF16(c[t],     al0, al1, al2, al3, bh0, bh1);
                MMA_BF16(c[t + 1], ah0, ah1, ah2, ah3, bh2, bh3);
                MMA_BF16(c[t + 1], ah0, ah1, ah2, ah3, bl2, bl3);
                MMA_BF16(c[t + 1], al0, al1, al2, al3, bh2, bh3);
                aB += 16 * STR * 2;
            }
        }
        __syncthreads();
    }

    const int gid = lane >> 2;
    const int tig = lane & 3;
    const int row0 = rowBase + R0 + gid;
    const int row1 = row0 + 8;

    float s0[2] = {0.f, 0.f}, s1[2] = {0.f, 0.f};
    float d0[2] = {0.f, 0.f}, d1[2] = {0.f, 0.f};
#pragma unroll
    for (int t = 0; t < 16; t++) {
        const int col = N0 + t * 8 + tig * 2;
        const int hh = t >> 3;
        float as0 = __ldg(&att_src[col]), as1 = __ldg(&att_src[col + 1]);
        float ad0 = __ldg(&att_dst[col]), ad1 = __ldg(&att_dst[col + 1]);
        s0[hh] += c[t][0] * as0 + c[t][1] * as1;
        s1[hh] += c[t][2] * as0 + c[t][3] * as1;
        d0[hh] += c[t][0] * ad0 + c[t][1] * ad1;
        d1[hh] += c[t][2] * ad0 + c[t][3] * ad1;
        if (row0 < NN) {
            __half2 p = __floats2half2_rn(c[t][0], c[t][1]);
            *(__half2*)&g_hh[(size_t)row0 * HC + col] = p;
        }
        if (row1 < NN) {
            __half2 p = __floats2half2_rn(c[t][2], c[t][3]);
            *(__half2*)&g_hh[(size_t)row1 * HC + col] = p;
        }
    }
#pragma unroll
    for (int hh = 0; hh < 2; hh++) {
        s0[hh] += __shfl_xor_sync(0xffffffffu, s0[hh], 1);
        s0[hh] += __shfl_xor_sync(0xffffffffu, s0[hh], 2);
        s1[hh] += __shfl_xor_sync(0xffffffffu, s1[hh], 1);
        s1[hh] += __shfl_xor_sync(0xffffffffu, s1[hh], 2);
        d0[hh] += __shfl_xor_sync(0xffffffffu, d0[hh], 1);
        d0[hh] += __shfl_xor_sync(0xffffffffu, d0[hh], 2);
        d1[hh] += __shfl_xor_sync(0xffffffffu, d1[hh], 1);
        d1[hh] += __shfl_xor_sync(0xffffffffu, d1[hh], 2);
    }
    if (tig == 0) {
        const int hbase = wc * 2;
#pragma unroll
        for (int hh = 0; hh < 2; hh++) {
            if (row0 < NN) {
                g_asrc[row0 * HEADS + hbase + hh] = s0[hh];
                g_adst[row0 * HEADS + hbase + hh] = d0[hh];
            }
            if (row1 < NN) {
                g_asrc[row1 * HEADS + hbase + hh] = s1[hh];
                g_adst[row1 * HEADS + hbase + hh] = d1[hh];
            }
        }
    }
}

// ---------------- 2) edge pass: denominator accumulation + out zero -------------
__global__ void edge_kernel(const void* __restrict__ ei, float* __restrict__ out)
{
    int e = blockIdx.x * blockDim.x + threadIdx.x;
    if (e < NN * OUTC / 4)
        ((float4*)out)[e] = make_float4(0.f, 0.f, 0.f, 0.f);
    if (e >= ET) return;
    int src, dst;
    if (e < NE) {
        src = edge_at(ei, e);
        dst = edge_at(ei, (long long)NE + e);
    } else {
        src = dst = e - NE;
    }
    float4 as = *(const float4*)&g_asrc[src * HEADS];
    float4 ad = *(const float4*)&g_adst[dst * HEADS];
    float4 ex;
    ex.x = __expf(lrelu(as.x + ad.x));
    ex.y = __expf(lrelu(as.y + ad.y));
    ex.z = __expf(lrelu(as.z + ad.z));
    ex.w = __expf(lrelu(as.w + ad.w));
    red_add_v4(&g_den[dst * HEADS], ex);
}

// ---------------- 3) weighted scatter: 8 lanes/edge, LDG.128, fp32 math ---------
__global__ __launch_bounds__(256) void scatter_kernel(
    const void* __restrict__ ei, float* __restrict__ out)
{
    const int gtid = blockIdx.x * blockDim.x + threadIdx.x;
    const int warp = gtid >> 5;
    const int lane = threadIdx.x & 31;
    const int eh = lane >> 3;       // 0..3: edge within warp
    const int j = lane & 7;         // 0..7: channel-octet
    const long long e = (long long)warp * 4 + eh;
    const bool valid = (e < ET);
    const long long ec = valid ? e : (ET - 1);

    int src = 0, dst = 0;
    float a0 = 0.f, a1 = 0.f, a2 = 0.f, a3 = 0.f;
    if (j == 0) {
        if (ec < NE) {
            src = edge_at(ei, ec);
            dst = edge_at(ei, (long long)NE + ec);
        } else {
            src = dst = (int)(ec - NE);
        }
        float4 as = *(const float4*)&g_asrc[src * HEADS];
        float4 ad = *(const float4*)&g_adst[dst * HEADS];
        float4 dn = *(const float4*)&g_den[dst * HEADS];
        a0 = 0.25f * __fdividef(__expf(lrelu(as.x + ad.x)), dn.x);
        a1 = 0.25f * __fdividef(__expf(lrelu(as.y + ad.y)), dn.y);
        a2 = 0.25f * __fdividef(__expf(lrelu(as.z + ad.z)), dn.z);
        a3 = 0.25f * __fdividef(__expf(lrelu(as.w + ad.w)), dn.w);
    }
    const int ls = eh << 3;
    src = __shfl_sync(0xffffffffu, src, ls);
    dst = __shfl_sync(0xffffffffu, dst, ls);
    a0 = __shfl_sync(0xffffffffu, a0, ls);
    a1 = __shfl_sync(0xffffffffu, a1, ls);
    a2 = __shfl_sync(0xffffffffu, a2, ls);
    a3 = __shfl_sync(0xffffffffu, a3, ls);

    // fp16 h row = 32 uint4 (8 per head). lane j handles channels 8j..8j+7.
    const uint4* r4 = (const uint4*)(g_hh + (size_t)src * HC);
    uint4 u0 = r4[j];
    uint4 u1 = r4[8 + j];
    uint4 u2 = r4[16 + j];
    uint4 u3 = r4[24 + j];

    float v[8];
    float2 f;
    // head 0 (init)
    f = __half22float2(*(const __half2*)&u0.x); v[0] = a0 * f.x; v[1] = a0 * f.y;
    f = __half22float2(*(const __half2*)&u0.y); v[2] = a0 * f.x; v[3] = a0 * f.y;
    f = __half22float2(*(const __half2*)&u0.z); v[4] = a0 * f.x; v[5] = a0 * f.y;
    f = __half22float2(*(const __half2*)&u0.w); v[6] = a0 * f.x; v[7] = a0 * f.y;
    // head 1
    f = __half22float2(*(const __half2*)&u1.x); v[0] = fmaf(a1, f.x, v[0]); v[1] = fmaf(a1, f.y, v[1]);
    f = __half22float2(*(const __half2*)&u1.y); v[2] = fmaf(a1, f.x, v[2]); v[3] = fmaf(a1, f.y, v[3]);
    f = __half22float2(*(const __half2*)&u1.z); v[4] = fmaf(a1, f.x, v[4]); v[5] = fmaf(a1, f.y, v[5]);
    f = __half22float2(*(const __half2*)&u1.w); v[6] = fmaf(a1, f.x, v[6]); v[7] = fmaf(a1, f.y, v[7]);
    // head 2
    f = __half22float2(*(const __half2*)&u2.x); v[0] = fmaf(a2, f.x, v[0]); v[1] = fmaf(a2, f.y, v[1]);
    f = __half22float2(*(const __half2*)&u2.y); v[2] = fmaf(a2, f.x, v[2]); v[3] = fmaf(a2, f.y, v[3]);
    f = __half22float2(*(const __half2*)&u2.z); v[4] = fmaf(a2, f.x, v[4]); v[5] = fmaf(a2, f.y, v[5]);
    f = __half22float2(*(const __half2*)&u2.w); v[6] = fmaf(a2, f.x, v[6]); v[7] = fmaf(a2, f.y, v[7]);
    // head 3
    f = __half22float2(*(const __half2*)&u3.x); v[0] = fmaf(a3, f.x, v[0]); v[1] = fmaf(a3, f.y, v[1]);
    f = __half22float2(*(const __half2*)&u3.y); v[2] = fmaf(a3, f.x, v[2]); v[3] = fmaf(a3, f.y, v[3]);
    f = __half22float2(*(const __half2*)&u3.z); v[4] = fmaf(a3, f.x, v[4]); v[5] = fmaf(a3, f.y, v[5]);
    f = __half22float2(*(const __half2*)&u3.w); v[6] = fmaf(a3, f.x, v[6]); v[7] = fmaf(a3, f.y, v[7]);

    if (valid) {
        float* op = &out[(size_t)dst * OUTC + 8 * j];
        red_add_v4(op,     make_float4(v[0], v[1], v[2], v[3]));
        red_add_v4(op + 4, make_float4(v[4], v[5], v[6], v[7]));
    }
}

// ---------------- 4) finalize ------------------------------------------------------
__global__ void final_kernel(float* __restrict__ out, const float* __restrict__ bias)
{
    int i = blockIdx.x * blockDim.x + threadIdx.x;
    if (i >= NN * OUTC) return;
    float v = out[i] + bias[i & (OUTC - 1)];
    out[i] = fmaxf(v, 0.0f);
}

// ---------------- launch --------------------------------------------------------
extern "C" void kernel_launch(void* const* d_in, const int* in_sizes, int n_in,
                              void* d_out, int out_size)
{
    const float* x       = (const float*)d_in[0];
    const void*  ei      = d_in[1];
    const float* W       = (const float*)d_in[2];
    const float* att_src = (const float*)d_in[3];
    const float* att_dst = (const float*)d_in[4];
    const float* bias    = (const float*)d_in[5];
    float* out = (float*)d_out;

    cudaFuncSetAttribute(gemm_tc_kernel,
                         cudaFuncAttributeMaxDynamicSharedMemorySize, GSMEM);

    gemm_tc_kernel<<<(NN + 127) / 128, 512, GSMEM>>>(x, W, att_src, att_dst); // idx 0
    detect_kernel<<<1, 256>>>((const int*)ei);                        // idx 1
    edge_kernel<<<(ET + 255) / 256, 256>>>(ei, out);                  // idx 2
    scatter_kernel<<<((size_t)ET * 8 + 255) / 256, 256>>>(ei, out);   // idx 3 (profiled)
    final_kernel<<<(NN * OUTC + 255) / 256, 256>>>(out, bias);        // idx 4
}

// round 14
// speedup vs baseline: 1.5838x; 1.0092x over previous
#include <cuda_runtime.h>
#include <cuda_bf16.h>
#include <cuda_fp16.h>
#include <math.h>
#include <cstdint>

#define NN 50000
#define NE 800000
#define INC 128
#define OUTC 64
#define HEADS 4
#define HC (HEADS * OUTC)   // 256
#define NEG_SLOPE 0.2f
#define ET (NE + NN)

// ---------------- scratch ------------------------------------------------------
__device__ __half g_hh[(size_t)NN * HC];    // projected features, fp16
__device__ float g_asrc[NN * HEADS];
__device__ float g_adst[NN * HEADS];
__device__ float g_den[NN * HEADS];
__device__ int   g_is64;

// ---------------- helpers ------------------------------------------------------
__device__ __forceinline__ float lrelu(float v) {
    return v >= 0.0f ? v : NEG_SLOPE * v;
}
__device__ __forceinline__ int edge_at(const void* ei, long long idx) {
    if (g_is64) return (int)((const long long*)ei)[idx];
    return ((const int*)ei)[idx];
}
__device__ __forceinline__ void red_add_v4(float* addr, float4 v) {
    asm volatile("red.global.add.v4.f32 [%0], {%1, %2, %3, %4};"
                 :: "l"(addr), "f"(v.x), "f"(v.y), "f"(v.z), "f"(v.w)
                 : "memory");
}
__device__ __forceinline__ uint32_t smem_to_u32(const void* p) {
    uint32_t a;
    asm("{ .reg .u64 t; cvta.to.shared.u64 t, %1; cvt.u32.u64 %0, t; }"
        : "=r"(a) : "l"(p));
    return a;
}
__device__ __forceinline__ uint32_t pack_bf16x2(float lo, float hi) {
    __nv_bfloat162 p(__float2bfloat16(lo), __float2bfloat16(hi));
    return *(uint32_t*)&p;
}
__device__ __forceinline__ float bf_round(float v) {
    return __bfloat162float(__float2bfloat16(v));
}

#define LDSM_X4(r0, r1, r2, r3, a) \
    asm volatile("ldmatrix.sync.aligned.m8n8.x4.shared.b16 {%0,%1,%2,%3}, [%4];" \
                 : "=r"(r0), "=r"(r1), "=r"(r2), "=r"(r3) : "r"(a))

#define MMA_BF16(c, a0, a1, a2, a3, b0, b1) \
    asm volatile("mma.sync.aligned.m16n8k16.row.col.f32.bf16.bf16.f32 " \
                 "{%0,%1,%2,%3}, {%4,%5,%6,%7}, {%8,%9}, {%0,%1,%2,%3};" \
                 : "+f"((c)[0]), "+f"((c)[1]), "+f"((c)[2]), "+f"((c)[3]) \
                 : "r"(a0), "r"(a1), "r"(a2), "r"(a3), "r"(b0), "r"(b1))

// ---------------- 0) dtype detection -------------------------------------------
__global__ void detect_kernel(const int* __restrict__ ei_raw) {
    __shared__ int nz;
    if (threadIdx.x == 0) nz = 0;
    __syncthreads();
    int local = 0;
    for (int i = threadIdx.x; i < 4096; i += blockDim.x)
        if (ei_raw[2 * i + 1] != 0) local = 1;
    if (local) atomicOr(&nz, 1);
    __syncthreads();
    if (threadIdx.x == 0) g_is64 = (nz == 0) ? 1 : 0;
}

// ---------------- 1) HMMA split-bf16 GEMM + fused attention halves --------------
// CTA 512 thr: tile M=128 x N=256, K chunks of 32. Warp tile M=32 x N=64 (4x4).
#define KCH 32
#define STR 40
#define AH_OFF 0
#define AL_OFF 10240
#define BH_OFF 20480
#define BL_OFF 40960
#define GSMEM 61440

__global__ __launch_bounds__(512) void gemm_tc_kernel(
    const float* __restrict__ x, const float* __restrict__ W,
    const float* __restrict__ att_src, const float* __restrict__ att_dst)
{
    {
        int zi = blockIdx.x * 512 + threadIdx.x;
        if (zi < NN * HEADS) g_den[zi] = 0.0f;
    }

    extern __shared__ char smem[];
    const uint32_t sbase = smem_to_u32(smem);
    const int tid = threadIdx.x;
    const int wid = tid >> 5;
    const int lane = tid & 31;
    const int rowBase = blockIdx.x * 128;

    const int wr = wid & 3;          // 4 row groups of 32
    const int wc = wid >> 2;         // 4 col groups of 64 (= head wc)
    const int R0 = wr * 32;
    const int N0 = wc * 64;

    const int lrow = lane & 7;
    const int quad = lane >> 3;

    // A frag base (m-tile 0, ks=0)
    const uint32_t addrA0 = sbase + AH_OFF +
        ((R0 + (quad & 1) * 8 + lrow) * STR + (quad >> 1) * 8) * 2;
    // B frag base (n-tilepair 0, ks=0)
    const uint32_t addrB0 = sbase + BH_OFF +
        ((N0 + (quad >> 1) * 8 + lrow) * STR + (quad & 1) * 8) * 2;

    // c[t]: t = m*8 + nt, m in 0..1 (m-tiles of 16 rows), nt in 0..7 (8-col tiles)
    float c[16][4];
#pragma unroll
    for (int t = 0; t < 16; t++)
#pragma unroll
        for (int q = 0; q < 4; q++) c[t][q] = 0.0f;

    const int xrow = tid >> 2;
    const int xkp = (tid & 3) * 8;
    const int wrow = tid >> 1;
    const int wkp = (tid & 1) * 16;

    for (int kc = 0; kc < 4; kc++) {
        const int k0 = kc * KCH;
        {
            int gr = rowBase + xrow;
            float4 v0 = make_float4(0.f, 0.f, 0.f, 0.f), v1 = v0;
            if (gr < NN) {
                const float4* xp = (const float4*)(x + (size_t)gr * INC + k0 + xkp);
                v0 = __ldg(&xp[0]);
                v1 = __ldg(&xp[1]);
            }
            float f[8] = {v0.x, v0.y, v0.z, v0.w, v1.x, v1.y, v1.z, v1.w};
            uint32_t* ah = (uint32_t*)(smem + AH_OFF + (xrow * STR + xkp) * 2);
            uint32_t* al = (uint32_t*)(smem + AL_OFF + (xrow * STR + xkp) * 2);
#pragma unroll
            for (int j = 0; j < 4; j++) {
                float a = f[2 * j], b = f[2 * j + 1];
                ah[j] = pack_bf16x2(a, b);
                al[j] = pack_bf16x2(a - bf_round(a), b - bf_round(b));
            }
        }
        {
            const float4* wp = (const float4*)(W + (size_t)wrow * INC + k0 + wkp);
            float4 v0 = __ldg(&wp[0]);
            float4 v1 = __ldg(&wp[1]);
            float4 v2 = __ldg(&wp[2]);
            float4 v3 = __ldg(&wp[3]);
            float f[16] = {v0.x, v0.y, v0.z, v0.w, v1.x, v1.y, v1.z, v1.w,
                           v2.x, v2.y, v2.z, v2.w, v3.x, v3.y, v3.z, v3.w};
            uint32_t* bh = (uint32_t*)(smem + BH_OFF + (wrow * STR + wkp) * 2);
            uint32_t* bl = (uint32_t*)(smem + BL_OFF + (wrow * STR + wkp) * 2);
#pragma unroll
            for (int j = 0; j < 8; j++) {
                float a = f[2 * j], b = f[2 * j + 1];
                bh[j] = pack_bf16x2(a, b);
                bl[j] = pack_bf16x2(a - bf_round(a), b - bf_round(b));
            }
        }
        __syncthreads();

#pragma unroll
        for (int ks = 0; ks < 2; ks++) {
            // A fragments for both m-tiles (h and l)
            uint32_t ah[2][4], al[2][4];
#pragma unroll
            for (int m = 0; m < 2; m++) {
                const uint32_t aA = addrA0 + ks * 32 + m * (16 * STR * 2);
                LDSM_X4(ah[m][0], ah[m][1], ah[m][2], ah[m][3], aA);
                LDSM_X4(al[m][0], al[m][1], al[m][2], al[m][3], aA + AL_OFF);
            }

            uint32_t aB = addrB0 + ks * 32;
#pragma unroll
            for (int tp = 0; tp < 4; tp++) {      // 4 n-tilepairs of 16 cols
                uint32_t bh0, bh1, bh2, bh3, bl0, bl1, bl2, bl3;
                LDSM_X4(bh0, bh1, bh2, bh3, aB);
                LDSM_X4(bl0, bl1, bl2, bl3, aB + 20480);
#pragma unroll
                for (int m = 0; m < 2; m++) {
                    const int t = m * 8 + tp * 2;
                    MMA_BF16(c[t],     ah[m][0], ah[m][1], ah[m][2], ah[m][3], bh0, bh1);
                    MMA_BF16(c[t],     ah[m][0], ah[m][1], ah[m][2], ah[m][3], bl0, bl1);
                    MMA_BF16(c[t],     al[m][0], al[m][1], al[m][2], al[m][3], bh0, bh1);
                    MMA_BF16(c[t + 1], ah[m][0], ah[m][1], ah[m][2], ah[m][3], bh2, bh3);
                    MMA_BF16(c[t + 1], ah[m][0], ah[m][1], ah[m][2], ah[m][3], bl2, bl3);
                    MMA_BF16(c[t + 1], al[m][0], al[m][1], al[m][2], al[m][3], bh2, bh3);
                }
                aB += 16 * STR * 2;
            }
        }
        __syncthreads();
    }

    // ---- epilogue: this warp's 64 cols = head wc ----
    const int gid = lane >> 2;
    const int tig = lane & 3;

#pragma unroll
    for (int m = 0; m < 2; m++) {
        const int ra = rowBase + R0 + m * 16 + gid;    // c rows {0,1}
        const int rb = ra + 8;                          // c rows {2,3}
        float sa = 0.f, sb = 0.f, da = 0.f, db = 0.f;
#pragma unroll
        for (int nt = 0; nt < 8; nt++) {
            const int t = m * 8 + nt;
            const int col = N0 + nt * 8 + tig * 2;
            float as0 = __ldg(&att_src[col]), as1 = __ldg(&att_src[col + 1]);
            float ad0 = __ldg(&att_dst[col]), ad1 = __ldg(&att_dst[col + 1]);
            sa += c[t][0] * as0 + c[t][1] * as1;
            sb += c[t][2] * as0 + c[t][3] * as1;
            da += c[t][0] * ad0 + c[t][1] * ad1;
            db += c[t][2] * ad0 + c[t][3] * ad1;
            if (ra < NN)
                *(__half2*)&g_hh[(size_t)ra * HC + col] = __floats2half2_rn(c[t][0], c[t][1]);
            if (rb < NN)
                *(__half2*)&g_hh[(size_t)rb * HC + col] = __floats2half2_rn(c[t][2], c[t][3]);
        }
        sa += __shfl_xor_sync(0xffffffffu, sa, 1);
        sa += __shfl_xor_sync(0xffffffffu, sa, 2);
        sb += __shfl_xor_sync(0xffffffffu, sb, 1);
        sb += __shfl_xor_sync(0xffffffffu, sb, 2);
        da += __shfl_xor_sync(0xffffffffu, da, 1);
        da += __shfl_xor_sync(0xffffffffu, da, 2);
        db += __shfl_xor_sync(0xffffffffu, db, 1);
        db += __shfl_xor_sync(0xffffffffu, db, 2);
        if (tig == 0) {
            if (ra < NN) {
                g_asrc[ra * HEADS + wc] = sa;
                g_adst[ra * HEADS + wc] = da;
            }
            if (rb < NN) {
                g_asrc[rb * HEADS + wc] = sb;
                g_adst[rb * HEADS + wc] = db;
            }
        }
    }
}

// ---------------- 2) edge pass: denominator accumulation + out zero -------------
__global__ void edge_kernel(const void* __restrict__ ei, float* __restrict__ out)
{
    int e = blockIdx.x * blockDim.x + threadIdx.x;
    if (e < NN * OUTC / 4)
        ((float4*)out)[e] = make_float4(0.f, 0.f, 0.f, 0.f);
    if (e >= ET) return;
    int src, dst;
    if (e < NE) {
        src = edge_at(ei, e);
        dst = edge_at(ei, (long long)NE + e);
    } else {
        src = dst = e - NE;
    }
    float4 as = *(const float4*)&g_asrc[src * HEADS];
    float4 ad = *(const float4*)&g_adst[dst * HEADS];
    float4 ex;
    ex.x = __expf(lrelu(as.x + ad.x));
    ex.y = __expf(lrelu(as.y + ad.y));
    ex.z = __expf(lrelu(as.z + ad.z));
    ex.w = __expf(lrelu(as.w + ad.w));
    red_add_v4(&g_den[dst * HEADS], ex);
}

// ---------------- 3) weighted scatter: 8 lanes/edge, LDG.128, fp32 math ---------
__global__ __launch_bounds__(256) void scatter_kernel(
    const void* __restrict__ ei, float* __restrict__ out)
{
    const int gtid = blockIdx.x * blockDim.x + threadIdx.x;
    const int warp = gtid >> 5;
    const int lane = threadIdx.x & 31;
    const int eh = lane >> 3;
    const int j = lane & 7;
    const long long e = (long long)warp * 4 + eh;
    const bool valid = (e < ET);
    const long long ec = valid ? e : (ET - 1);

    int src = 0, dst = 0;
    float a0 = 0.f, a1 = 0.f, a2 = 0.f, a3 = 0.f;
    if (j == 0) {
        if (ec < NE) {
            src = edge_at(ei, ec);
            dst = edge_at(ei, (long long)NE + ec);
        } else {
            src = dst = (int)(ec - NE);
        }
        float4 as = *(const float4*)&g_asrc[src * HEADS];
        float4 ad = *(const float4*)&g_adst[dst * HEADS];
        float4 dn = *(const float4*)&g_den[dst * HEADS];
        a0 = 0.25f * __fdividef(__expf(lrelu(as.x + ad.x)), dn.x);
        a1 = 0.25f * __fdividef(__expf(lrelu(as.y + ad.y)), dn.y);
        a2 = 0.25f * __fdividef(__expf(lrelu(as.z + ad.z)), dn.z);
        a3 = 0.25f * __fdividef(__expf(lrelu(as.w + ad.w)), dn.w);
    }
    const int ls = eh << 3;
    src = __shfl_sync(0xffffffffu, src, ls);
    dst = __shfl_sync(0xffffffffu, dst, ls);
    a0 = __shfl_sync(0xffffffffu, a0, ls);
    a1 = __shfl_sync(0xffffffffu, a1, ls);
    a2 = __shfl_sync(0xffffffffu, a2, ls);
    a3 = __shfl_sync(0xffffffffu, a3, ls);

    const uint4* r4 = (const uint4*)(g_hh + (size_t)src * HC);
    uint4 u0 = r4[j];
    uint4 u1 = r4[8 + j];
    uint4 u2 = r4[16 + j];
    uint4 u3 = r4[24 + j];

    float v[8];
    float2 f;
    f = __half22float2(*(const __half2*)&u0.x); v[0] = a0 * f.x; v[1] = a0 * f.y;
    f = __half22float2(*(const __half2*)&u0.y); v[2] = a0 * f.x; v[3] = a0 * f.y;
    f = __half22float2(*(const __half2*)&u0.z); v[4] = a0 * f.x; v[5] = a0 * f.y;
    f = __half22float2(*(const __half2*)&u0.w); v[6] = a0 * f.x; v[7] = a0 * f.y;
    f = __half22float2(*(const __half2*)&u1.x); v[0] = fmaf(a1, f.x, v[0]); v[1] = fmaf(a1, f.y, v[1]);
    f = __half22float2(*(const __half2*)&u1.y); v[2] = fmaf(a1, f.x, v[2]); v[3] = fmaf(a1, f.y, v[3]);
    f = __half22float2(*(const __half2*)&u1.z); v[4] = fmaf(a1, f.x, v[4]); v[5] = fmaf(a1, f.y, v[5]);
    f = __half22float2(*(const __half2*)&u1.w); v[6] = fmaf(a1, f.x, v[6]); v[7] = fmaf(a1, f.y, v[7]);
    f = __half22float2(*(const __half2*)&u2.x); v[0] = fmaf(a2, f.x, v[0]); v[1] = fmaf(a2, f.y, v[1]);
    f = __half22float2(*(const __half2*)&u2.y); v[2] = fmaf(a2, f.x, v[2]); v[3] = fmaf(a2, f.y, v[3]);
    f = __half22float2(*(const __half2*)&u2.z); v[4] = fmaf(a2, f.x, v[4]); v[5] = fmaf(a2, f.y, v[5]);
    f = __half22float2(*(const __half2*)&u2.w); v[6] = fmaf(a2, f.x, v[6]); v[7] = fmaf(a2, f.y, v[7]);
    f = __half22float2(*(const __half2*)&u3.x); v[0] = fmaf(a3, f.x, v[0]); v[1] = fmaf(a3, f.y, v[1]);
    f = __half22float2(*(const __half2*)&u3.y); v[2] = fmaf(a3, f.x, v[2]); v[3] = fmaf(a3, f.y, v[3]);
    f = __half22float2(*(const __half2*)&u3.z); v[4] = fmaf(a3, f.x, v[4]); v[5] = fmaf(a3, f.y, v[5]);
    f = __half22float2(*(const __half2*)&u3.w); v[6] = fmaf(a3, f.x, v[6]); v[7] = fmaf(a3, f.y, v[7]);

    if (valid) {
        float* op = &out[(size_t)dst * OUTC + 8 * j];
        red_add_v4(op,     make_float4(v[0], v[1], v[2], v[3]));
        red_add_v4(op + 4, make_float4(v[4], v[5], v[6], v[7]));
    }
}

// ---------------- 4) finalize ------------------------------------------------------
__global__ void final_kernel(float* __restrict__ out, const float* __restrict__ bias)
{
    int i = blockIdx.x * blockDim.x + threadIdx.x;
    if (i >= NN * OUTC) return;
    float v = out[i] + bias[i & (OUTC - 1)];
    out[i] = fmaxf(v, 0.0f);
}

// ---------------- launch --------------------------------------------------------
extern "C" void kernel_launch(void* const* d_in, const int* in_sizes, int n_in,
                              void* d_out, int out_size)
{
    const float* x       = (const float*)d_in[0];
    const void*  ei      = d_in[1];
    const float* W       = (const float*)d_in[2];
    const float* att_src = (const float*)d_in[3];
    const float* att_dst = (const float*)d_in[4];
    const float* bias    = (const float*)d_in[5];
    float* out = (float*)d_out;

    cudaFuncSetAttribute(gemm_tc_kernel,
                         cudaFuncAttributeMaxDynamicSharedMemorySize, GSMEM);

    detect_kernel<<<1, 256>>>((const int*)ei);                        // idx 0
    zero: ;
    gemm_tc_kernel<<<(NN + 127) / 128, 512, GSMEM>>>(x, W, att_src, att_dst); // idx 1
    edge_kernel<<<(ET + 255) / 256, 256>>>(ei, out);                  // idx 2
    gemm_profiled: ;
    scatter_kernel<<<((size_t)ET * 8 + 255) / 256, 256>>>(ei, out);   // idx 3 (profiled)
    final_kernel<<<(NN * OUTC + 255) / 256, 256>>>(out, bias);        // idx 4
}